// round 3
// baseline (speedup 1.0000x reference)
#include <cuda_runtime.h>
#include <math.h>

#define Bc   32
#define Ssz  201
#define SL   200
#define Hdim 512
#define Vdim 32000
#define Mrows (Bc*SL)   // 6400

// ---------------- scratch (static device globals; no allocation) ------------
__device__ __align__(16) float g_hidden[Mrows*Hdim];
__device__ __align__(16) float g_head  [Mrows*Hdim];
__device__ __align__(16) float g_tail  [Mrows*Hdim];
__device__ __align__(16) float g_depend[Mrows*Hdim];
__device__ __align__(16) float g_enc   [Mrows*Hdim];
__device__ __align__(16) float g_map1  [Mrows*Hdim];
__device__ __align__(16) float g_ti    [Mrows*Hdim];
__device__ __align__(16) float g_aout  [Mrows*Hdim];
__device__ int g_caslen[Bc];

__device__ __forceinline__ float elu_f(float x){ return x > 0.f ? x : (expf(x) - 1.f); }

// ---------------- cas_len -----------------------------------------------
__global__ void caslen_k(const int* __restrict__ cas){
    int b = blockIdx.x, tid = threadIdx.x;
    int c = (tid < SL && cas[b*Ssz + tid] != 0) ? 1 : 0;
    for (int o = 16; o; o >>= 1) c += __shfl_xor_sync(0xffffffffu, c, o);
    __shared__ int s[8];
    if ((tid & 31) == 0) s[tid >> 5] = c;
    __syncthreads();
    if (tid == 0) { int t = 0; for (int q = 0; q < 8; q++) t += s[q]; g_caslen[b] = t; }
}

// ---------------- tiled SGEMM -------------------------------------------
// C[M,N] = act(A[M,K] @ Bw[K,N] + bias) (* row mask).
// GATHER=1: A row r = table[idx[(r/SL)*Ssz + r%SL]] (embedding / time_lambda gather)
// ACT: 0 none, 1 elu.  MASK: multiply row by (i < cas_len[b]).
#define BM 128
#define BN 128
#define BKK 16
#define TM 8
#define TN 8

template<int ACT, int GATHER, int MASK>
__global__ __launch_bounds__(256) void sgemm_k(
    const float* __restrict__ A, const float* __restrict__ table,
    const int* __restrict__ idx, const float* __restrict__ Bw,
    const float* __restrict__ bias, float* __restrict__ C,
    int M, int N, int K, int ldb, int ldc)
{
    __shared__ float As[BKK][BM];
    __shared__ float Bs[BKK][BN];
    int bn = blockIdx.x, bm = blockIdx.y;
    int tid = threadIdx.x;
    int tr = (tid >> 4) * TM, tc = (tid & 15) * TN;

    float acc[TM][TN];
    #pragma unroll
    for (int m = 0; m < TM; m++)
        #pragma unroll
        for (int n = 0; n < TN; n++) acc[m][n] = 0.f;

    // A loader: this thread loads float4 #tid and #(tid+256) of the 128x16 tile
    int lrow0 = tid >> 2, lc4 = tid & 3;       // rows lrow0 and lrow0+64
    const float *ap0, *ap1;
    {
        int gr0 = bm*BM + lrow0, gr1 = gr0 + 64;
        if (GATHER) {
            ap0 = table + (size_t)idx[(gr0/SL)*Ssz + (gr0%SL)] * K;
            ap1 = table + (size_t)idx[(gr1/SL)*Ssz + (gr1%SL)] * K;
        } else {
            ap0 = A + (size_t)gr0 * K;
            ap1 = A + (size_t)gr1 * K;
        }
    }
    // B loader: rows bkrow0 and bkrow0+8 of the 16x128 tile
    int bkrow0 = tid >> 5, bc4 = tid & 31;
    const float* bp = Bw + (size_t)bn*BN + bc4*4;

    for (int k0 = 0; k0 < K; k0 += BKK) {
        float4 a0 = *(const float4*)(ap0 + k0 + lc4*4);
        float4 a1 = *(const float4*)(ap1 + k0 + lc4*4);
        float4 b0 = *(const float4*)(bp + (size_t)(k0 + bkrow0    ) * ldb);
        float4 b1 = *(const float4*)(bp + (size_t)(k0 + bkrow0 + 8) * ldb);
        __syncthreads();
        As[lc4*4+0][lrow0] = a0.x; As[lc4*4+1][lrow0] = a0.y;
        As[lc4*4+2][lrow0] = a0.z; As[lc4*4+3][lrow0] = a0.w;
        As[lc4*4+0][lrow0+64] = a1.x; As[lc4*4+1][lrow0+64] = a1.y;
        As[lc4*4+2][lrow0+64] = a1.z; As[lc4*4+3][lrow0+64] = a1.w;
        *(float4*)&Bs[bkrow0  ][bc4*4] = b0;
        *(float4*)&Bs[bkrow0+8][bc4*4] = b1;
        __syncthreads();
        #pragma unroll
        for (int kk = 0; kk < BKK; kk++) {
            float ar[TM], br[TN];
            *(float4*)(ar  ) = *(float4*)&As[kk][tr  ];
            *(float4*)(ar+4) = *(float4*)&As[kk][tr+4];
            *(float4*)(br  ) = *(float4*)&Bs[kk][tc  ];
            *(float4*)(br+4) = *(float4*)&Bs[kk][tc+4];
            #pragma unroll
            for (int m = 0; m < TM; m++)
                #pragma unroll
                for (int n = 0; n < TN; n++)
                    acc[m][n] = fmaf(ar[m], br[n], acc[m][n]);
        }
    }

    #pragma unroll
    for (int m = 0; m < TM; m++) {
        int r = bm*BM + tr + m;
        float msk = 1.f;
        if (MASK) {
            int bb = r / SL, ii = r % SL;
            msk = (ii < g_caslen[bb]) ? 1.f : 0.f;
        }
        #pragma unroll
        for (int n = 0; n < TN; n++) {
            int c = bn*BN + tc + n;
            float v = acc[m][n] + bias[c];
            if (ACT == 1) v = elu_f(v);
            if (MASK) v *= msk;
            C[(size_t)r * ldc + c] = v;
        }
    }
}

// ---------------- gate GEMM (K=1024 concat [hidden|depend]) + enc -------
__global__ __launch_bounds__(256) void gate_k(
    const float* __restrict__ Bw, const float* __restrict__ bias)
{
    __shared__ float As[BKK][BM];
    __shared__ float Bs[BKK][BN];
    int bn = blockIdx.x, bm = blockIdx.y;
    int tid = threadIdx.x;
    int tr = (tid >> 4) * TM, tc = (tid & 15) * TN;

    float acc[TM][TN];
    #pragma unroll
    for (int m = 0; m < TM; m++)
        #pragma unroll
        for (int n = 0; n < TN; n++) acc[m][n] = 0.f;

    int lrow0 = tid >> 2, lc4 = tid & 3;
    int gr0 = bm*BM + lrow0, gr1 = gr0 + 64;
    int bkrow0 = tid >> 5, bc4 = tid & 31;
    const float* bp = Bw + (size_t)bn*BN + bc4*4;   // ldb = Hdim

    for (int k0 = 0; k0 < 2*Hdim; k0 += BKK) {
        const float* src = (k0 < Hdim) ? g_hidden : g_depend;
        int koff = (k0 < Hdim) ? k0 : (k0 - Hdim);
        float4 a0 = *(const float4*)(src + (size_t)gr0*Hdim + koff + lc4*4);
        float4 a1 = *(const float4*)(src + (size_t)gr1*Hdim + koff + lc4*4);
        float4 b0 = *(const float4*)(bp + (size_t)(k0 + bkrow0    ) * Hdim);
        float4 b1 = *(const float4*)(bp + (size_t)(k0 + bkrow0 + 8) * Hdim);
        __syncthreads();
        As[lc4*4+0][lrow0] = a0.x; As[lc4*4+1][lrow0] = a0.y;
        As[lc4*4+2][lrow0] = a0.z; As[lc4*4+3][lrow0] = a0.w;
        As[lc4*4+0][lrow0+64] = a1.x; As[lc4*4+1][lrow0+64] = a1.y;
        As[lc4*4+2][lrow0+64] = a1.z; As[lc4*4+3][lrow0+64] = a1.w;
        *(float4*)&Bs[bkrow0  ][bc4*4] = b0;
        *(float4*)&Bs[bkrow0+8][bc4*4] = b1;
        __syncthreads();
        #pragma unroll
        for (int kk = 0; kk < BKK; kk++) {
            float ar[TM], br[TN];
            *(float4*)(ar  ) = *(float4*)&As[kk][tr  ];
            *(float4*)(ar+4) = *(float4*)&As[kk][tr+4];
            *(float4*)(br  ) = *(float4*)&Bs[kk][tc  ];
            *(float4*)(br+4) = *(float4*)&Bs[kk][tc+4];
            #pragma unroll
            for (int m = 0; m < TM; m++)
                #pragma unroll
                for (int n = 0; n < TN; n++)
                    acc[m][n] = fmaf(ar[m], br[n], acc[m][n]);
        }
    }

    #pragma unroll
    for (int m = 0; m < TM; m++) {
        int r = bm*BM + tr + m;
        int bb = r / SL, ii = r % SL;
        float msk = (ii < g_caslen[bb]) ? 1.f : 0.f;
        #pragma unroll
        for (int n = 0; n < TN; n++) {
            int c = bn*BN + tc + n;
            float g = 1.f / (1.f + expf(-(acc[m][n] + bias[c])));
            float h = g_hidden[(size_t)r*Hdim + c];
            float d = g_depend[(size_t)r*Hdim + c];
            g_enc[(size_t)r*Hdim + c] = (g*h + (1.f - g)*d) * msk;
        }
    }
}

// ---------------- attention: logits -> softmax -> depend ----------------
__global__ __launch_bounds__(256) void attn_k()
{
    int i = blockIdx.x, b = blockIdx.y;
    size_t r = (size_t)b*SL + i;
    int len = g_caslen[b];
    int jmax = min(i, len);              // valid j: j < i AND j < len (contiguous)
    int tid = threadIdx.x, w = tid >> 5, l = tid & 31;

    if (jmax == 0) {
        for (int h = tid; h < Hdim; h += 256) g_depend[r*Hdim + h] = 0.f;
        return;
    }

    __shared__ float hrow[Hdim];
    __shared__ float sc[SL];
    __shared__ float red[8];

    for (int h = tid; h < Hdim; h += 256) hrow[h] = g_head[r*Hdim + h];
    __syncthreads();

    for (int j = w; j < jmax; j += 8) {
        const float* trow = g_tail + ((size_t)b*SL + j)*Hdim;
        float s = 0.f;
        #pragma unroll 4
        for (int h = l; h < Hdim; h += 32) s = fmaf(hrow[h], trow[h], s);
        for (int o = 16; o; o >>= 1) s += __shfl_xor_sync(0xffffffffu, s, o);
        if (l == 0) sc[j] = s;
    }
    __syncthreads();

    // max
    float m = -1e30f;
    for (int j = tid; j < jmax; j += 256) m = fmaxf(m, sc[j]);
    for (int o = 16; o; o >>= 1) m = fmaxf(m, __shfl_xor_sync(0xffffffffu, m, o));
    if (l == 0) red[w] = m;
    __syncthreads();
    if (tid == 0) { float mm = red[0]; for (int q = 1; q < 8; q++) mm = fmaxf(mm, red[q]); red[0] = mm; }
    __syncthreads();
    m = red[0];

    // exp + sum
    float ssum = 0.f;
    for (int j = tid; j < jmax; j += 256) { float e = expf(sc[j] - m); sc[j] = e; ssum += e; }
    for (int o = 16; o; o >>= 1) ssum += __shfl_xor_sync(0xffffffffu, ssum, o);
    __syncthreads();                  // all done reading red[0] / writing sc
    if (l == 0) red[w] = ssum;
    __syncthreads();
    if (tid == 0) { float t = 0.f; for (int q = 0; q < 8; q++) t += red[q]; red[0] = t; }
    __syncthreads();
    float inv = 1.f / red[0];

    // depend[h] = inv * sum_j sc[j] * hidden[b,j,h]
    for (int h = tid; h < Hdim; h += 256) {
        float acc = 0.f;
        const float* hp = g_hidden + (size_t)b*SL*Hdim + h;
        for (int j = 0; j < jmax; j++) acc = fmaf(sc[j], hp[(size_t)j*Hdim], acc);
        g_depend[r*Hdim + h] = acc * inv;
    }
}

// ---------------- pool: map2 dot, masked softmax over i, Aout = pool*enc -
__global__ __launch_bounds__(256) void pool_k(
    const float* __restrict__ wm2, const float* __restrict__ bm2)
{
    int b = blockIdx.x, tid = threadIdx.x, w = tid >> 5, l = tid & 31;
    __shared__ float m2[SL];
    __shared__ float red[8];
    int len = g_caslen[b];

    for (int i = w; i < SL; i += 8) {
        size_t r = (size_t)b*SL + i;
        float s = 0.f;
        #pragma unroll 4
        for (int h = l; h < Hdim; h += 32)
            s = fmaf(g_map1[r*Hdim + h] * g_ti[r*Hdim + h], wm2[h], s);
        for (int o = 16; o; o >>= 1) s += __shfl_xor_sync(0xffffffffu, s, o);
        if (l == 0) m2[i] = s + bm2[0];
    }
    __syncthreads();

    float mx = -1e30f;
    for (int i = tid; i < len; i += 256) mx = fmaxf(mx, m2[i]);
    for (int o = 16; o; o >>= 1) mx = fmaxf(mx, __shfl_xor_sync(0xffffffffu, mx, o));
    if (l == 0) red[w] = mx;
    __syncthreads();
    if (tid == 0) { float mm = red[0]; for (int q = 1; q < 8; q++) mm = fmaxf(mm, red[q]); red[0] = mm; }
    __syncthreads();
    mx = red[0];

    float sum = 0.f;
    for (int i = tid; i < len; i += 256) { float e = expf(m2[i] - mx); m2[i] = e; sum += e; }
    for (int o = 16; o; o >>= 1) sum += __shfl_xor_sync(0xffffffffu, sum, o);
    __syncthreads();
    if (l == 0) red[w] = sum;
    __syncthreads();
    if (tid == 0) { float t = 0.f; for (int q = 0; q < 8; q++) t += red[q]; red[0] = t; }
    __syncthreads();
    float inv = (len > 0) ? 1.f / red[0] : 0.f;

    for (int i = tid; i < SL; i += 256) m2[i] = (i < len) ? m2[i]*inv : 0.f;
    __syncthreads();

    size_t base = (size_t)b*SL*Hdim;
    for (int e = tid; e < SL*Hdim; e += 256) {
        int i = e >> 9;   // /Hdim
        g_aout[base + e] = m2[i] * g_enc[base + e];
    }
}

// ---------------- launch ------------------------------------------------
extern "C" void kernel_launch(void* const* d_in, const int* in_sizes, int n_in,
                              void* d_out, int out_size)
{
    const int*   cas  = (const int*)  d_in[0];
    const int*   tii  = (const int*)  d_in[1];
    const float* emb  = (const float*)d_in[2];
    const float* tlam = (const float*)d_in[3];
    const float* w1   = (const float*)d_in[4];
    const float* b1   = (const float*)d_in[5];
    const float* wh   = (const float*)d_in[6];
    const float* bh   = (const float*)d_in[7];
    const float* wt   = (const float*)d_in[8];
    const float* bt   = (const float*)d_in[9];
    const float* wg   = (const float*)d_in[10];
    const float* bg   = (const float*)d_in[11];
    const float* wm1  = (const float*)d_in[12];
    const float* bm1  = (const float*)d_in[13];
    const float* wti  = (const float*)d_in[14];
    const float* bti  = (const float*)d_in[15];
    const float* wm2  = (const float*)d_in[16];
    const float* bm2  = (const float*)d_in[17];
    const float* wout = (const float*)d_in[18];
    const float* bout = (const float*)d_in[19];
    float* out = (float*)d_out;

    float *hid, *hed, *tal, *enc_, *m1, *tip, *ao;
    cudaGetSymbolAddress((void**)&hid,  g_hidden);
    cudaGetSymbolAddress((void**)&hed,  g_head);
    cudaGetSymbolAddress((void**)&tal,  g_tail);
    cudaGetSymbolAddress((void**)&enc_, g_enc);
    cudaGetSymbolAddress((void**)&m1,   g_map1);
    cudaGetSymbolAddress((void**)&tip,  g_ti);
    cudaGetSymbolAddress((void**)&ao,   g_aout);

    caslen_k<<<Bc, 256>>>(cas);

    dim3 g512(Hdim/BN, Mrows/BM);       // (4, 50)
    // hidden = elu(gather(emb)@w1 + b1) * mask
    sgemm_k<1,1,1><<<g512, 256>>>(nullptr, emb, cas, w1, b1, hid,
                                  Mrows, Hdim, Hdim, Hdim, Hdim);
    // head / tail
    sgemm_k<0,0,0><<<g512, 256>>>(hid, nullptr, nullptr, wh, bh, hed,
                                  Mrows, Hdim, Hdim, Hdim, Hdim);
    sgemm_k<0,0,0><<<g512, 256>>>(hid, nullptr, nullptr, wt, bt, tal,
                                  Mrows, Hdim, Hdim, Hdim, Hdim);
    // attention -> depend
    attn_k<<<dim3(SL, Bc), 256>>>();
    // gate + enc
    gate_k<<<g512, 256>>>(wg, bg);
    // map1 = elu(enc@wm1 + bm1)
    sgemm_k<1,0,0><<<g512, 256>>>(enc_, nullptr, nullptr, wm1, bm1, m1,
                                  Mrows, Hdim, Hdim, Hdim, Hdim);
    // ti = elu(gather(time_lambda)@wti + bti)
    sgemm_k<1,1,0><<<g512, 256>>>(nullptr, tlam, tii, wti, bti, tip,
                                  Mrows, Hdim, Hdim, Hdim, Hdim);
    // pool + Aout = pool * enc
    pool_k<<<Bc, 256>>>(wm2, bm2);
    // final: out = Aout @ wout + bout
    dim3 gout(Vdim/BN, Mrows/BM);       // (250, 50)
    sgemm_k<0,0,0><<<gout, 256>>>(ao, nullptr, nullptr, wout, bout, out,
                                  Mrows, Vdim, Hdim, Vdim, Vdim);
}

// round 6
// speedup vs baseline: 1.9858x; 1.9858x over previous
#include <cuda_runtime.h>
#include <cuda_bf16.h>
#include <math.h>
#include <stdint.h>

#define Bc   32
#define Ssz  201
#define SL   200
#define Hdim 512
#define Vdim 32000
#define Mrows (Bc*SL)   // 6400

// ---------------- scratch (static device globals; no allocation) ------------
__device__ __align__(16) float g_hidden[Mrows*Hdim];
__device__ __align__(16) float g_head  [Mrows*Hdim];
__device__ __align__(16) float g_tail  [Mrows*Hdim];
__device__ __align__(16) float g_depend[Mrows*Hdim];
__device__ __align__(16) float g_enc   [Mrows*Hdim];
__device__ __align__(16) float g_map1  [Mrows*Hdim];
__device__ __align__(16) float g_ti    [Mrows*Hdim];
__device__ __align__(16) float g_aout  [Mrows*Hdim];
__device__ int g_caslen[Bc];

// bf16 split operands for the tensor-core final GEMM
__device__ __align__(16) __nv_bfloat16 g_a_hi[Mrows*Hdim];
__device__ __align__(16) __nv_bfloat16 g_a_lo[Mrows*Hdim];
__device__ __align__(16) __nv_bfloat16 g_w_hi[(size_t)Vdim*Hdim];  // [V, H] K-major
__device__ __align__(16) __nv_bfloat16 g_w_lo[(size_t)Vdim*Hdim];

__device__ __forceinline__ float elu_f(float x){ return x > 0.f ? x : (expf(x) - 1.f); }

// ========================= mma helpers =====================================
__device__ __forceinline__ uint32_t smem_u32(const void* p){
    uint32_t a;
    asm("{ .reg .u64 t; cvta.to.shared.u64 t, %1; cvt.u32.u64 %0, t; }" : "=r"(a) : "l"(p));
    return a;
}
#define SWZ128(off) ((off) ^ (((off) >> 3) & 0x70))

__device__ __forceinline__ void cpa16(uint32_t s, const void* g){
    asm volatile("cp.async.cg.shared.global [%0], [%1], 16;" :: "r"(s), "l"(g));
}

#define LDSM4(r0, r1, r2, r3, addr) \
    asm volatile("ldmatrix.sync.aligned.m8n8.x4.shared.b16 {%0,%1,%2,%3}, [%4];" \
        : "=r"(r0), "=r"(r1), "=r"(r2), "=r"(r3) : "r"(addr))

#define MMA16816(c, a, b0, b1) \
    asm volatile("mma.sync.aligned.m16n8k16.row.col.f32.bf16.bf16.f32 " \
        "{%0,%1,%2,%3},{%4,%5,%6,%7},{%8,%9},{%0,%1,%2,%3};" \
        : "+f"((c)[0]), "+f"((c)[1]), "+f"((c)[2]), "+f"((c)[3]) \
        : "r"((a)[0]), "r"((a)[1]), "r"((a)[2]), "r"((a)[3]), "r"(b0), "r"(b1))

// ---------------- cas_len -----------------------------------------------
__global__ void caslen_k(const int* __restrict__ cas){
    int b = blockIdx.x, tid = threadIdx.x;
    int c = (tid < SL && cas[b*Ssz + tid] != 0) ? 1 : 0;
    for (int o = 16; o; o >>= 1) c += __shfl_xor_sync(0xffffffffu, c, o);
    __shared__ int s[8];
    if ((tid & 31) == 0) s[tid >> 5] = c;
    __syncthreads();
    if (tid == 0) { int t = 0; for (int q = 0; q < 8; q++) t += s[q]; g_caslen[b] = t; }
}

// ---------------- tiled SGEMM (mid stages, fp32) -------------------------
#define BM 128
#define BN 128
#define BKK 16
#define TM 8
#define TN 8

template<int ACT, int GATHER, int MASK>
__global__ __launch_bounds__(256) void sgemm_k(
    const float* __restrict__ A, const float* __restrict__ table,
    const int* __restrict__ idx, const float* __restrict__ Bw,
    const float* __restrict__ bias, float* __restrict__ C,
    int M, int N, int K, int ldb, int ldc)
{
    __shared__ float As[BKK][BM];
    __shared__ float Bs[BKK][BN];
    int bn = blockIdx.x, bm = blockIdx.y;
    int tid = threadIdx.x;
    int tr = (tid >> 4) * TM, tc = (tid & 15) * TN;

    float acc[TM][TN];
    #pragma unroll
    for (int m = 0; m < TM; m++)
        #pragma unroll
        for (int n = 0; n < TN; n++) acc[m][n] = 0.f;

    int lrow0 = tid >> 2, lc4 = tid & 3;
    const float *ap0, *ap1;
    {
        int gr0 = bm*BM + lrow0, gr1 = gr0 + 64;
        if (GATHER) {
            ap0 = table + (size_t)idx[(gr0/SL)*Ssz + (gr0%SL)] * K;
            ap1 = table + (size_t)idx[(gr1/SL)*Ssz + (gr1%SL)] * K;
        } else {
            ap0 = A + (size_t)gr0 * K;
            ap1 = A + (size_t)gr1 * K;
        }
    }
    int bkrow0 = tid >> 5, bc4 = tid & 31;
    const float* bp = Bw + (size_t)bn*BN + bc4*4;

    for (int k0 = 0; k0 < K; k0 += BKK) {
        float4 a0 = *(const float4*)(ap0 + k0 + lc4*4);
        float4 a1 = *(const float4*)(ap1 + k0 + lc4*4);
        float4 b0 = *(const float4*)(bp + (size_t)(k0 + bkrow0    ) * ldb);
        float4 b1 = *(const float4*)(bp + (size_t)(k0 + bkrow0 + 8) * ldb);
        __syncthreads();
        As[lc4*4+0][lrow0] = a0.x; As[lc4*4+1][lrow0] = a0.y;
        As[lc4*4+2][lrow0] = a0.z; As[lc4*4+3][lrow0] = a0.w;
        As[lc4*4+0][lrow0+64] = a1.x; As[lc4*4+1][lrow0+64] = a1.y;
        As[lc4*4+2][lrow0+64] = a1.z; As[lc4*4+3][lrow0+64] = a1.w;
        *(float4*)&Bs[bkrow0  ][bc4*4] = b0;
        *(float4*)&Bs[bkrow0+8][bc4*4] = b1;
        __syncthreads();
        #pragma unroll
        for (int kk = 0; kk < BKK; kk++) {
            float ar[TM], br[TN];
            *(float4*)(ar  ) = *(float4*)&As[kk][tr  ];
            *(float4*)(ar+4) = *(float4*)&As[kk][tr+4];
            *(float4*)(br  ) = *(float4*)&Bs[kk][tc  ];
            *(float4*)(br+4) = *(float4*)&Bs[kk][tc+4];
            #pragma unroll
            for (int m = 0; m < TM; m++)
                #pragma unroll
                for (int n = 0; n < TN; n++)
                    acc[m][n] = fmaf(ar[m], br[n], acc[m][n]);
        }
    }

    #pragma unroll
    for (int m = 0; m < TM; m++) {
        int r = bm*BM + tr + m;
        float msk = 1.f;
        if (MASK) {
            int bb = r / SL, ii = r % SL;
            msk = (ii < g_caslen[bb]) ? 1.f : 0.f;
        }
        #pragma unroll
        for (int n = 0; n < TN; n++) {
            int c = bn*BN + tc + n;
            float v = acc[m][n] + bias[c];
            if (ACT == 1) v = elu_f(v);
            if (MASK) v *= msk;
            C[(size_t)r * ldc + c] = v;
        }
    }
}

// ---------------- gate GEMM (K=1024 concat [hidden|depend]) + enc -------
__global__ __launch_bounds__(256) void gate_k(
    const float* __restrict__ Bw, const float* __restrict__ bias)
{
    __shared__ float As[BKK][BM];
    __shared__ float Bs[BKK][BN];
    int bn = blockIdx.x, bm = blockIdx.y;
    int tid = threadIdx.x;
    int tr = (tid >> 4) * TM, tc = (tid & 15) * TN;

    float acc[TM][TN];
    #pragma unroll
    for (int m = 0; m < TM; m++)
        #pragma unroll
        for (int n = 0; n < TN; n++) acc[m][n] = 0.f;

    int lrow0 = tid >> 2, lc4 = tid & 3;
    int gr0 = bm*BM + lrow0, gr1 = gr0 + 64;
    int bkrow0 = tid >> 5, bc4 = tid & 31;
    const float* bp = Bw + (size_t)bn*BN + bc4*4;

    for (int k0 = 0; k0 < 2*Hdim; k0 += BKK) {
        const float* src = (k0 < Hdim) ? g_hidden : g_depend;
        int koff = (k0 < Hdim) ? k0 : (k0 - Hdim);
        float4 a0 = *(const float4*)(src + (size_t)gr0*Hdim + koff + lc4*4);
        float4 a1 = *(const float4*)(src + (size_t)gr1*Hdim + koff + lc4*4);
        float4 b0 = *(const float4*)(bp + (size_t)(k0 + bkrow0    ) * Hdim);
        float4 b1 = *(const float4*)(bp + (size_t)(k0 + bkrow0 + 8) * Hdim);
        __syncthreads();
        As[lc4*4+0][lrow0] = a0.x; As[lc4*4+1][lrow0] = a0.y;
        As[lc4*4+2][lrow0] = a0.z; As[lc4*4+3][lrow0] = a0.w;
        As[lc4*4+0][lrow0+64] = a1.x; As[lc4*4+1][lrow0+64] = a1.y;
        As[lc4*4+2][lrow0+64] = a1.z; As[lc4*4+3][lrow0+64] = a1.w;
        *(float4*)&Bs[bkrow0  ][bc4*4] = b0;
        *(float4*)&Bs[bkrow0+8][bc4*4] = b1;
        __syncthreads();
        #pragma unroll
        for (int kk = 0; kk < BKK; kk++) {
            float ar[TM], br[TN];
            *(float4*)(ar  ) = *(float4*)&As[kk][tr  ];
            *(float4*)(ar+4) = *(float4*)&As[kk][tr+4];
            *(float4*)(br  ) = *(float4*)&Bs[kk][tc  ];
            *(float4*)(br+4) = *(float4*)&Bs[kk][tc+4];
            #pragma unroll
            for (int m = 0; m < TM; m++)
                #pragma unroll
                for (int n = 0; n < TN; n++)
                    acc[m][n] = fmaf(ar[m], br[n], acc[m][n]);
        }
    }

    #pragma unroll
    for (int m = 0; m < TM; m++) {
        int r = bm*BM + tr + m;
        int bb = r / SL, ii = r % SL;
        float msk = (ii < g_caslen[bb]) ? 1.f : 0.f;
        #pragma unroll
        for (int n = 0; n < TN; n++) {
            int c = bn*BN + tc + n;
            float g = 1.f / (1.f + expf(-(acc[m][n] + bias[c])));
            float h = g_hidden[(size_t)r*Hdim + c];
            float d = g_depend[(size_t)r*Hdim + c];
            g_enc[(size_t)r*Hdim + c] = (g*h + (1.f - g)*d) * msk;
        }
    }
}

// ---------------- attention: logits -> softmax -> depend ----------------
__global__ __launch_bounds__(256) void attn_k()
{
    int i = blockIdx.x, b = blockIdx.y;
    size_t r = (size_t)b*SL + i;
    int len = g_caslen[b];
    int jmax = min(i, len);
    int tid = threadIdx.x, w = tid >> 5, l = tid & 31;

    if (jmax == 0) {
        for (int h = tid; h < Hdim; h += 256) g_depend[r*Hdim + h] = 0.f;
        return;
    }

    __shared__ float hrow[Hdim];
    __shared__ float sc[SL];
    __shared__ float red[8];

    for (int h = tid; h < Hdim; h += 256) hrow[h] = g_head[r*Hdim + h];
    __syncthreads();

    for (int j = w; j < jmax; j += 8) {
        const float* trow = g_tail + ((size_t)b*SL + j)*Hdim;
        float s = 0.f;
        #pragma unroll 4
        for (int h = l; h < Hdim; h += 32) s = fmaf(hrow[h], trow[h], s);
        for (int o = 16; o; o >>= 1) s += __shfl_xor_sync(0xffffffffu, s, o);
        if (l == 0) sc[j] = s;
    }
    __syncthreads();

    float m = -1e30f;
    for (int j = tid; j < jmax; j += 256) m = fmaxf(m, sc[j]);
    for (int o = 16; o; o >>= 1) m = fmaxf(m, __shfl_xor_sync(0xffffffffu, m, o));
    if (l == 0) red[w] = m;
    __syncthreads();
    if (tid == 0) { float mm = red[0]; for (int q = 1; q < 8; q++) mm = fmaxf(mm, red[q]); red[0] = mm; }
    __syncthreads();
    m = red[0];

    float ssum = 0.f;
    for (int j = tid; j < jmax; j += 256) { float e = expf(sc[j] - m); sc[j] = e; ssum += e; }
    for (int o = 16; o; o >>= 1) ssum += __shfl_xor_sync(0xffffffffu, ssum, o);
    __syncthreads();
    if (l == 0) red[w] = ssum;
    __syncthreads();
    if (tid == 0) { float t = 0.f; for (int q = 0; q < 8; q++) t += red[q]; red[0] = t; }
    __syncthreads();
    float inv = 1.f / red[0];

    for (int h = tid; h < Hdim; h += 256) {
        float acc = 0.f;
        const float* hp = g_hidden + (size_t)b*SL*Hdim + h;
        for (int j = 0; j < jmax; j++) acc = fmaf(sc[j], hp[(size_t)j*Hdim], acc);
        g_depend[r*Hdim + h] = acc * inv;
    }
}

// ---------------- pool ---------------------------------------------------
__global__ __launch_bounds__(256) void pool_k(
    const float* __restrict__ wm2, const float* __restrict__ bm2)
{
    int b = blockIdx.x, tid = threadIdx.x, w = tid >> 5, l = tid & 31;
    __shared__ float m2[SL];
    __shared__ float red[8];
    int len = g_caslen[b];

    for (int i = w; i < SL; i += 8) {
        size_t r = (size_t)b*SL + i;
        float s = 0.f;
        #pragma unroll 4
        for (int h = l; h < Hdim; h += 32)
            s = fmaf(g_map1[r*Hdim + h] * g_ti[r*Hdim + h], wm2[h], s);
        for (int o = 16; o; o >>= 1) s += __shfl_xor_sync(0xffffffffu, s, o);
        if (l == 0) m2[i] = s + bm2[0];
    }
    __syncthreads();

    float mx = -1e30f;
    for (int i = tid; i < len; i += 256) mx = fmaxf(mx, m2[i]);
    for (int o = 16; o; o >>= 1) mx = fmaxf(mx, __shfl_xor_sync(0xffffffffu, mx, o));
    if (l == 0) red[w] = mx;
    __syncthreads();
    if (tid == 0) { float mm = red[0]; for (int q = 1; q < 8; q++) mm = fmaxf(mm, red[q]); red[0] = mm; }
    __syncthreads();
    mx = red[0];

    float sum = 0.f;
    for (int i = tid; i < len; i += 256) { float e = expf(m2[i] - mx); m2[i] = e; sum += e; }
    for (int o = 16; o; o >>= 1) sum += __shfl_xor_sync(0xffffffffu, sum, o);
    __syncthreads();
    if (l == 0) red[w] = sum;
    __syncthreads();
    if (tid == 0) { float t = 0.f; for (int q = 0; q < 8; q++) t += red[q]; red[0] = t; }
    __syncthreads();
    float inv = (len > 0) ? 1.f / red[0] : 0.f;

    for (int i = tid; i < SL; i += 256) m2[i] = (i < len) ? m2[i]*inv : 0.f;
    __syncthreads();

    size_t base = (size_t)b*SL*Hdim;
    for (int e = tid; e < SL*Hdim; e += 256) {
        int i = e >> 9;
        g_aout[base + e] = m2[i] * g_enc[base + e];
    }
}

// ---------------- bf16 split conversions ---------------------------------
__global__ void splitA_k(){
    int i = blockIdx.x*256 + threadIdx.x;
    float v = g_aout[i];
    __nv_bfloat16 h = __float2bfloat16(v);
    g_a_hi[i] = h;
    g_a_lo[i] = __float2bfloat16(v - __bfloat162float(h));
}

// wout [Hdim, Vdim] row-major -> g_w_hi/lo [Vdim, Hdim] (K-major), split
__global__ void splitW_k(const float* __restrict__ wout){
    __shared__ float t[32][33];
    int n0 = blockIdx.x*32, k0 = blockIdx.y*32;
    int x = threadIdx.x, y = threadIdx.y;       // block (32, 8)
    for (int i = y; i < 32; i += 8)
        t[i][x] = wout[(size_t)(k0+i)*Vdim + n0 + x];
    __syncthreads();
    for (int nn = y; nn < 32; nn += 8) {
        float v = t[x][nn];
        __nv_bfloat16 h = __float2bfloat16(v);
        size_t o = (size_t)(n0+nn)*Hdim + k0 + x;
        g_w_hi[o] = h;
        g_w_lo[o] = __float2bfloat16(v - __bfloat162float(h));
    }
}

// ---------------- mma.sync bf16 final GEMM -------------------------------
// C[6400, 32000] = (ah+al)[M,512] @ (wh+wl)^T + bias   (W stored [N,K])
// C = ah*wh + al*wh + ah*wl (3-term split). CTA tile 128x256, K chunks of 64.
#define GM 128
#define GN 256
#define GK 64
#define NGK (Hdim/GK)          // 8
#define OFF_AH 0
#define OFF_AL 16384
#define OFF_BH 32768
#define OFF_BL 65536
#define STG_STRIDE 98304
#define SMEM_MM (2*STG_STRIDE)   // 196608

__device__ __forceinline__ void load_chunk_mm(uint32_t sb, int buf, int bm, int bn, int kc, int tid){
    const uint32_t base = sb + buf*STG_STRIDE;
    const __nv_bfloat16* Ah = g_a_hi + (size_t)(bm*GM)*Hdim + kc*GK;
    const __nv_bfloat16* Al = g_a_lo + (size_t)(bm*GM)*Hdim + kc*GK;
    #pragma unroll
    for (int t = 0; t < 4; t++) {               // A: 128 rows x 8 granules
        int G = tid + t*256; int r = G >> 3, g = G & 7;
        uint32_t d = SWZ128((uint32_t)(r*128 + g*16));
        cpa16(base + OFF_AH + d, Ah + (size_t)r*Hdim + g*8);
        cpa16(base + OFF_AL + d, Al + (size_t)r*Hdim + g*8);
    }
    const __nv_bfloat16* Bh = g_w_hi + (size_t)(bn*GN)*Hdim + kc*GK;
    const __nv_bfloat16* Bl = g_w_lo + (size_t)(bn*GN)*Hdim + kc*GK;
    #pragma unroll
    for (int t = 0; t < 8; t++) {               // B: 256 rows x 8 granules
        int G = tid + t*256; int r = G >> 3, g = G & 7;
        uint32_t d = SWZ128((uint32_t)(r*128 + g*16));
        cpa16(base + OFF_BH + d, Bh + (size_t)r*Hdim + g*8);
        cpa16(base + OFF_BL + d, Bl + (size_t)r*Hdim + g*8);
    }
    asm volatile("cp.async.commit_group;" ::: "memory");
}

__global__ __launch_bounds__(256) void gemm_mm_k(
    const float* __restrict__ bias, float* __restrict__ C)
{
    extern __shared__ char smem[];
    const int tid = threadIdx.x, lane = tid & 31, wid = tid >> 5;
    const int bm = blockIdx.x, bn = blockIdx.y;
    const int wm = wid & 1, wn = wid >> 1;      // warp grid 2(M) x 4(N), 64x64 each
    const int rl = lane & 15, gl = lane >> 4;
    uint32_t sb = smem_u32(smem);

    float acc[4][8][4];
    #pragma unroll
    for (int mi = 0; mi < 4; mi++)
        #pragma unroll
        for (int ni = 0; ni < 8; ni++)
            #pragma unroll
            for (int q = 0; q < 4; q++) acc[mi][ni][q] = 0.f;

    load_chunk_mm(sb, 0, bm, bn, 0, tid);
    load_chunk_mm(sb, 1, bm, bn, 1, tid);

    for (int kc = 0; kc < NGK; kc++) {
        if (kc < NGK-1) asm volatile("cp.async.wait_group 1;" ::: "memory");
        else            asm volatile("cp.async.wait_group 0;" ::: "memory");
        __syncthreads();

        const uint32_t base = sb + (kc & 1)*STG_STRIDE;
        const uint32_t ahb = base + OFF_AH, alb = base + OFF_AL;
        const uint32_t bhb = base + OFF_BH, blb = base + OFF_BL;

        #pragma unroll
        for (int ks = 0; ks < 4; ks++) {
            const int kg = 2*ks + gl;
            uint32_t Aa[4][4], Bb[4][4];
            // --- product 1: ah * wh ---
            #pragma unroll
            for (int mi = 0; mi < 4; mi++) {
                uint32_t ad = ahb + SWZ128((uint32_t)((wm*64 + mi*16 + rl)*128 + kg*16));
                LDSM4(Aa[mi][0], Aa[mi][1], Aa[mi][2], Aa[mi][3], ad);
            }
            #pragma unroll
            for (int np = 0; np < 4; np++) {
                uint32_t bd = bhb + SWZ128((uint32_t)((wn*64 + np*16 + rl)*128 + kg*16));
                LDSM4(Bb[np][0], Bb[np][1], Bb[np][2], Bb[np][3], bd);
            }
            #pragma unroll
            for (int mi = 0; mi < 4; mi++)
                #pragma unroll
                for (int np = 0; np < 4; np++) {
                    MMA16816(acc[mi][2*np  ], Aa[mi], Bb[np][0], Bb[np][2]);
                    MMA16816(acc[mi][2*np+1], Aa[mi], Bb[np][1], Bb[np][3]);
                }
            // --- product 2: al * wh (reuse Bb) ---
            uint32_t Al2[4][4];
            #pragma unroll
            for (int mi = 0; mi < 4; mi++) {
                uint32_t ad = alb + SWZ128((uint32_t)((wm*64 + mi*16 + rl)*128 + kg*16));
                LDSM4(Al2[mi][0], Al2[mi][1], Al2[mi][2], Al2[mi][3], ad);
            }
            #pragma unroll
            for (int mi = 0; mi < 4; mi++)
                #pragma unroll
                for (int np = 0; np < 4; np++) {
                    MMA16816(acc[mi][2*np  ], Al2[mi], Bb[np][0], Bb[np][2]);
                    MMA16816(acc[mi][2*np+1], Al2[mi], Bb[np][1], Bb[np][3]);
                }
            // --- product 3: ah * wl (reuse Aa, overwrite Bb) ---
            #pragma unroll
            for (int np = 0; np < 4; np++) {
                uint32_t bd = blb + SWZ128((uint32_t)((wn*64 + np*16 + rl)*128 + kg*16));
                LDSM4(Bb[np][0], Bb[np][1], Bb[np][2], Bb[np][3], bd);
            }
            #pragma unroll
            for (int mi = 0; mi < 4; mi++)
                #pragma unroll
                for (int np = 0; np < 4; np++) {
                    MMA16816(acc[mi][2*np  ], Aa[mi], Bb[np][0], Bb[np][2]);
                    MMA16816(acc[mi][2*np+1], Aa[mi], Bb[np][1], Bb[np][3]);
                }
        }
        __syncthreads();
        if (kc + 2 < NGK) load_chunk_mm(sb, kc & 1, bm, bn, kc + 2, tid);
    }

    // epilogue: fragment layout c0,c1 @ (row lane/4, col 2*(lane%4)), c2,c3 @ row+8
    const int m0 = bm*GM + wm*64 + (lane >> 2);
    const int n0 = bn*GN + wn*64 + 2*(lane & 3);
    #pragma unroll
    for (int mi = 0; mi < 4; mi++) {
        #pragma unroll
        for (int ni = 0; ni < 8; ni++) {
            int n = n0 + ni*8;
            float b0 = bias[n], b1 = bias[n+1];
            int m = m0 + mi*16;
            float2 v0 = make_float2(acc[mi][ni][0] + b0, acc[mi][ni][1] + b1);
            float2 v1 = make_float2(acc[mi][ni][2] + b0, acc[mi][ni][3] + b1);
            *(float2*)(C + (size_t)m*Vdim + n)     = v0;
            *(float2*)(C + (size_t)(m+8)*Vdim + n) = v1;
        }
    }
}

// ---------------- launch ------------------------------------------------
extern "C" void kernel_launch(void* const* d_in, const int* in_sizes, int n_in,
                              void* d_out, int out_size)
{
    const int*   cas  = (const int*)  d_in[0];
    const int*   tii  = (const int*)  d_in[1];
    const float* emb  = (const float*)d_in[2];
    const float* tlam = (const float*)d_in[3];
    const float* w1   = (const float*)d_in[4];
    const float* b1   = (const float*)d_in[5];
    const float* wh   = (const float*)d_in[6];
    const float* bh   = (const float*)d_in[7];
    const float* wt   = (const float*)d_in[8];
    const float* bt   = (const float*)d_in[9];
    const float* wg   = (const float*)d_in[10];
    const float* bg   = (const float*)d_in[11];
    const float* wm1  = (const float*)d_in[12];
    const float* bm1  = (const float*)d_in[13];
    const float* wti  = (const float*)d_in[14];
    const float* bti  = (const float*)d_in[15];
    const float* wm2  = (const float*)d_in[16];
    const float* bm2  = (const float*)d_in[17];
    const float* wout = (const float*)d_in[18];
    const float* bout = (const float*)d_in[19];
    float* out = (float*)d_out;

    float *hid, *hed, *tal, *enc_, *m1, *tip;
    cudaGetSymbolAddress((void**)&hid,  g_hidden);
    cudaGetSymbolAddress((void**)&hed,  g_head);
    cudaGetSymbolAddress((void**)&tal,  g_tail);
    cudaGetSymbolAddress((void**)&enc_, g_enc);
    cudaGetSymbolAddress((void**)&m1,   g_map1);
    cudaGetSymbolAddress((void**)&tip,  g_ti);

    cudaFuncSetAttribute(gemm_mm_k, cudaFuncAttributeMaxDynamicSharedMemorySize, SMEM_MM);

    caslen_k<<<Bc, 256>>>(cas);

    // W transpose+split is independent of everything else — do it early.
    splitW_k<<<dim3(Vdim/32, Hdim/32), dim3(32, 8)>>>(wout);

    dim3 g512(Hdim/BN, Mrows/BM);       // (4, 50)
    sgemm_k<1,1,1><<<g512, 256>>>(nullptr, emb, cas, w1, b1, hid,
                                  Mrows, Hdim, Hdim, Hdim, Hdim);
    sgemm_k<0,0,0><<<g512, 256>>>(hid, nullptr, nullptr, wh, bh, hed,
                                  Mrows, Hdim, Hdim, Hdim, Hdim);
    sgemm_k<0,0,0><<<g512, 256>>>(hid, nullptr, nullptr, wt, bt, tal,
                                  Mrows, Hdim, Hdim, Hdim, Hdim);
    attn_k<<<dim3(SL, Bc), 256>>>();
    gate_k<<<g512, 256>>>(wg, bg);
    sgemm_k<1,0,0><<<g512, 256>>>(enc_, nullptr, nullptr, wm1, bm1, m1,
                                  Mrows, Hdim, Hdim, Hdim, Hdim);
    sgemm_k<1,1,0><<<g512, 256>>>(nullptr, tlam, tii, wti, bti, tip,
                                  Mrows, Hdim, Hdim, Hdim, Hdim);
    pool_k<<<Bc, 256>>>(wm2, bm2);
    splitA_k<<<(Mrows*Hdim)/256, 256>>>();

    // final: out = (a_hi+a_lo) @ (w_hi+w_lo)^T + bout  via mma.sync bf16
    gemm_mm_k<<<dim3(Mrows/GM, Vdim/GN), 256, SMEM_MM>>>(bout, out);
}

// round 7
// speedup vs baseline: 3.7617x; 1.8943x over previous
#include <cuda_runtime.h>
#include <cuda_bf16.h>
#include <cuda_fp16.h>
#include <math.h>
#include <stdint.h>

#define Bc   32
#define Ssz  201
#define SL   200
#define Hdim 512
#define Vdim 32000
#define Mrows (Bc*SL)   // 6400

// ---------------- scratch (static device globals; no allocation) ------------
__device__ __align__(16) float g_hidden[Mrows*Hdim];
__device__ __align__(16) float g_head  [Mrows*Hdim];
__device__ __align__(16) float g_tail  [Mrows*Hdim];
__device__ __align__(16) float g_depend[Mrows*Hdim];
__device__ __align__(16) float g_enc   [Mrows*Hdim];
__device__ __align__(16) float g_map1  [Mrows*Hdim];
__device__ __align__(16) float g_ti    [Mrows*Hdim];
__device__ int g_caslen[Bc];

// bf16 split activations (hi/lo) for mid tensor-core GEMMs
__device__ __align__(16) __nv_bfloat16 g_emb_hi[Mrows*Hdim];
__device__ __align__(16) __nv_bfloat16 g_emb_lo[Mrows*Hdim];
__device__ __align__(16) __nv_bfloat16 g_tw_hi [Mrows*Hdim];
__device__ __align__(16) __nv_bfloat16 g_tw_lo [Mrows*Hdim];
__device__ __align__(16) __nv_bfloat16 g_hid_hi[Mrows*Hdim];
__device__ __align__(16) __nv_bfloat16 g_hid_lo[Mrows*Hdim];
__device__ __align__(16) __nv_bfloat16 g_dep_hi[Mrows*Hdim];
__device__ __align__(16) __nv_bfloat16 g_dep_lo[Mrows*Hdim];
__device__ __align__(16) __nv_bfloat16 g_enc_hi[Mrows*Hdim];
__device__ __align__(16) __nv_bfloat16 g_enc_lo[Mrows*Hdim];

// bf16 split transposed weights [N, K] K-major
__device__ __align__(16) __nv_bfloat16 g_w1T_h [Hdim*Hdim];
__device__ __align__(16) __nv_bfloat16 g_w1T_l [Hdim*Hdim];
__device__ __align__(16) __nv_bfloat16 g_whT_h [Hdim*Hdim];
__device__ __align__(16) __nv_bfloat16 g_whT_l [Hdim*Hdim];
__device__ __align__(16) __nv_bfloat16 g_wtT_h [Hdim*Hdim];
__device__ __align__(16) __nv_bfloat16 g_wtT_l [Hdim*Hdim];
__device__ __align__(16) __nv_bfloat16 g_wm1T_h[Hdim*Hdim];
__device__ __align__(16) __nv_bfloat16 g_wm1T_l[Hdim*Hdim];
__device__ __align__(16) __nv_bfloat16 g_wtiT_h[Hdim*Hdim];
__device__ __align__(16) __nv_bfloat16 g_wtiT_l[Hdim*Hdim];
__device__ __align__(16) __nv_bfloat16 g_wgT_h [Hdim*2*Hdim];  // [512, 1024]
__device__ __align__(16) __nv_bfloat16 g_wgT_l [Hdim*2*Hdim];

// fp16 operands for the final 1-term GEMM
__device__ __align__(16) __half g_a16[Mrows*Hdim];
__device__ __align__(16) __half g_w16[(size_t)Vdim*Hdim];   // [V, H] K-major

__device__ __forceinline__ float elu_f(float x){ return x > 0.f ? x : (expf(x) - 1.f); }

// ========================= mma helpers =====================================
__device__ __forceinline__ uint32_t smem_u32(const void* p){
    uint32_t a;
    asm("{ .reg .u64 t; cvta.to.shared.u64 t, %1; cvt.u32.u64 %0, t; }" : "=r"(a) : "l"(p));
    return a;
}
#define SWZ128(off) ((off) ^ (((off) >> 3) & 0x70))

__device__ __forceinline__ void cpa16(uint32_t s, const void* g){
    asm volatile("cp.async.cg.shared.global [%0], [%1], 16;" :: "r"(s), "l"(g));
}

#define LDSM4(r0, r1, r2, r3, addr) \
    asm volatile("ldmatrix.sync.aligned.m8n8.x4.shared.b16 {%0,%1,%2,%3}, [%4];" \
        : "=r"(r0), "=r"(r1), "=r"(r2), "=r"(r3) : "r"(addr))

#define MMABF(c, a, b0, b1) \
    asm volatile("mma.sync.aligned.m16n8k16.row.col.f32.bf16.bf16.f32 " \
        "{%0,%1,%2,%3},{%4,%5,%6,%7},{%8,%9},{%0,%1,%2,%3};" \
        : "+f"((c)[0]), "+f"((c)[1]), "+f"((c)[2]), "+f"((c)[3]) \
        : "r"((a)[0]), "r"((a)[1]), "r"((a)[2]), "r"((a)[3]), "r"(b0), "r"(b1))

#define MMAFP(c, a, b0, b1) \
    asm volatile("mma.sync.aligned.m16n8k16.row.col.f32.f16.f16.f32 " \
        "{%0,%1,%2,%3},{%4,%5,%6,%7},{%8,%9},{%0,%1,%2,%3};" \
        : "+f"((c)[0]), "+f"((c)[1]), "+f"((c)[2]), "+f"((c)[3]) \
        : "r"((a)[0]), "r"((a)[1]), "r"((a)[2]), "r"((a)[3]), "r"(b0), "r"(b1))

// ---------------- cas_len -----------------------------------------------
__global__ void caslen_k(const int* __restrict__ cas){
    int b = blockIdx.x, tid = threadIdx.x;
    int c = (tid < SL && cas[b*Ssz + tid] != 0) ? 1 : 0;
    for (int o = 16; o; o >>= 1) c += __shfl_xor_sync(0xffffffffu, c, o);
    __shared__ int s[8];
    if ((tid & 31) == 0) s[tid >> 5] = c;
    __syncthreads();
    if (tid == 0) { int t = 0; for (int q = 0; q < 8; q++) t += s[q]; g_caslen[b] = t; }
}

// ---------------- weight transpose + split -------------------------------
// w [Kdim, 512] row-major -> hi/lo [512, Kdim] K-major
__global__ void transW_bf16_k(const float* __restrict__ w,
                              __nv_bfloat16* __restrict__ hi,
                              __nv_bfloat16* __restrict__ lo, int Kdim){
    __shared__ float t[32][33];
    int n0 = blockIdx.x*32, k0 = blockIdx.y*32;
    int x = threadIdx.x, y = threadIdx.y;
    for (int i = y; i < 32; i += 8)
        t[i][x] = w[(size_t)(k0+i)*Hdim + n0 + x];
    __syncthreads();
    for (int nn = y; nn < 32; nn += 8) {
        float v = t[x][nn];
        __nv_bfloat16 h = __float2bfloat16(v);
        size_t o = (size_t)(n0+nn)*Kdim + k0 + x;
        hi[o] = h;
        lo[o] = __float2bfloat16(v - __bfloat162float(h));
    }
}

// wout [512, 32000] -> fp16 [32000, 512]
__global__ void transW_f16_k(const float* __restrict__ w, __half* __restrict__ out){
    __shared__ float t[32][33];
    int n0 = blockIdx.x*32, k0 = blockIdx.y*32;
    int x = threadIdx.x, y = threadIdx.y;
    for (int i = y; i < 32; i += 8)
        t[i][x] = w[(size_t)(k0+i)*Vdim + n0 + x];
    __syncthreads();
    for (int nn = y; nn < 32; nn += 8)
        out[(size_t)(n0+nn)*Hdim + k0 + x] = __float2half(t[x][nn]);
}

// gather table rows via idx, split to bf16 hi/lo [M, 512]
__global__ void gatherSplit_k(const float* __restrict__ table, const int* __restrict__ idx,
                              __nv_bfloat16* __restrict__ hi, __nv_bfloat16* __restrict__ lo){
    int i = blockIdx.x*256 + threadIdx.x;
    int r = i >> 9, c = i & 511;
    int row = idx[(r/SL)*Ssz + (r%SL)];
    float v = table[(size_t)row*Hdim + c];
    __nv_bfloat16 h = __float2bfloat16(v);
    hi[i] = h;
    lo[i] = __float2bfloat16(v - __bfloat162float(h));
}

// ---------------- mid bf16 3-term mma GEMM -------------------------------
// C[M, 512] = act( (Ah+Al)[M, K] @ (Wh+Wl)^T + bias )  (W [512, K] K-major)
// tile 128x128, KC=64, double buffered. A source switches at kc=8 (gate concat).
#define MGM 128
#define MGN 128
#define MKC 64
#define MOFF_AH 0
#define MOFF_AL 16384
#define MOFF_BH 32768
#define MOFF_BL 49152
#define MSTG 65536
#define SMEM_MG (2*MSTG)   // 131072

// EPI: 0 bias; 1 bias+elu+mask (+splits); 2 bias+elu; 3 sigmoid-gate combine+mask (+splits)
template<int EPI>
__device__ __forceinline__ void epi_store(float v, int r, int c,
    const float* __restrict__ bias, float* __restrict__ C,
    __nv_bfloat16* __restrict__ Chi, __nv_bfloat16* __restrict__ Clo)
{
    v += bias[c];
    if (EPI == 1 || EPI == 2) v = elu_f(v);
    if (EPI == 3) {
        float g = 1.f / (1.f + expf(-v));
        float h = g_hidden[(size_t)r*Hdim + c];
        float d = g_depend[(size_t)r*Hdim + c];
        v = g*h + (1.f - g)*d;
    }
    if (EPI == 1 || EPI == 3) {
        int bb = r / SL, ii = r % SL;
        if (ii >= g_caslen[bb]) v = 0.f;
    }
    C[(size_t)r*Hdim + c] = v;
    if (EPI == 1 || EPI == 3) {
        __nv_bfloat16 h = __float2bfloat16(v);
        Chi[(size_t)r*Hdim + c] = h;
        Clo[(size_t)r*Hdim + c] = __float2bfloat16(v - __bfloat162float(h));
    }
}

template<int EPI>
__global__ __launch_bounds__(256) void mgemm_k(
    const __nv_bfloat16* __restrict__ Ah0, const __nv_bfloat16* __restrict__ Al0,
    const __nv_bfloat16* __restrict__ Ah1, const __nv_bfloat16* __restrict__ Al1,
    const __nv_bfloat16* __restrict__ Wh,  const __nv_bfloat16* __restrict__ Wl,
    int ldw, int nkc,
    const float* __restrict__ bias, float* __restrict__ C,
    __nv_bfloat16* __restrict__ Chi, __nv_bfloat16* __restrict__ Clo)
{
    extern __shared__ char smem[];
    const int tid = threadIdx.x, lane = tid & 31, wid = tid >> 5;
    const int bn = blockIdx.x, bm = blockIdx.y;
    const int wm = wid & 1, wn = wid >> 1;     // 2(M) x 4(N) warps, each 64x32
    const int rl = lane & 15, gl = lane >> 4;
    uint32_t sb = smem_u32(smem);

    float acc[4][4][4];
    #pragma unroll
    for (int mi = 0; mi < 4; mi++)
        #pragma unroll
        for (int ni = 0; ni < 4; ni++)
            #pragma unroll
            for (int q = 0; q < 4; q++) acc[mi][ni][q] = 0.f;

    auto load_stage = [&](int kc, int buf){
        const __nv_bfloat16 *ah, *al; int koff;
        if (kc < 8) { ah = Ah0; al = Al0; koff = kc*MKC; }
        else        { ah = Ah1; al = Al1; koff = (kc-8)*MKC; }
        const __nv_bfloat16* ap_h = ah + (size_t)(bm*MGM)*Hdim + koff;
        const __nv_bfloat16* ap_l = al + (size_t)(bm*MGM)*Hdim + koff;
        const __nv_bfloat16* wp_h = Wh + (size_t)(bn*MGN)*ldw + kc*MKC;
        const __nv_bfloat16* wp_l = Wl + (size_t)(bn*MGN)*ldw + kc*MKC;
        uint32_t base = sb + buf*MSTG;
        #pragma unroll
        for (int t = 0; t < 4; t++) {
            int G = tid + t*256; int r = G >> 3, g = G & 7;
            uint32_t d = SWZ128((uint32_t)(r*128 + g*16));
            cpa16(base + MOFF_AH + d, ap_h + (size_t)r*Hdim + g*8);
            cpa16(base + MOFF_AL + d, ap_l + (size_t)r*Hdim + g*8);
            cpa16(base + MOFF_BH + d, wp_h + (size_t)r*ldw + g*8);
            cpa16(base + MOFF_BL + d, wp_l + (size_t)r*ldw + g*8);
        }
        asm volatile("cp.async.commit_group;" ::: "memory");
    };

    load_stage(0, 0);
    load_stage(1, 1);

    for (int kc = 0; kc < nkc; kc++) {
        if (kc < nkc-1) asm volatile("cp.async.wait_group 1;" ::: "memory");
        else            asm volatile("cp.async.wait_group 0;" ::: "memory");
        __syncthreads();
        const uint32_t base = sb + (kc & 1)*MSTG;
        #pragma unroll
        for (int ks = 0; ks < 4; ks++) {
            const int kg = 2*ks + gl;
            uint32_t Aa[4][4], Bb[2][4], Al2[4][4];
            #pragma unroll
            for (int mi = 0; mi < 4; mi++) {
                uint32_t ad = base + MOFF_AH + SWZ128((uint32_t)((wm*64 + mi*16 + rl)*128 + kg*16));
                LDSM4(Aa[mi][0], Aa[mi][1], Aa[mi][2], Aa[mi][3], ad);
            }
            #pragma unroll
            for (int np = 0; np < 2; np++) {
                uint32_t bd = base + MOFF_BH + SWZ128((uint32_t)((wn*32 + np*16 + rl)*128 + kg*16));
                LDSM4(Bb[np][0], Bb[np][1], Bb[np][2], Bb[np][3], bd);
            }
            #pragma unroll
            for (int mi = 0; mi < 4; mi++)
                #pragma unroll
                for (int np = 0; np < 2; np++) {
                    MMABF(acc[mi][2*np  ], Aa[mi], Bb[np][0], Bb[np][2]);
                    MMABF(acc[mi][2*np+1], Aa[mi], Bb[np][1], Bb[np][3]);
                }
            #pragma unroll
            for (int mi = 0; mi < 4; mi++) {
                uint32_t ad = base + MOFF_AL + SWZ128((uint32_t)((wm*64 + mi*16 + rl)*128 + kg*16));
                LDSM4(Al2[mi][0], Al2[mi][1], Al2[mi][2], Al2[mi][3], ad);
            }
            #pragma unroll
            for (int mi = 0; mi < 4; mi++)
                #pragma unroll
                for (int np = 0; np < 2; np++) {
                    MMABF(acc[mi][2*np  ], Al2[mi], Bb[np][0], Bb[np][2]);
                    MMABF(acc[mi][2*np+1], Al2[mi], Bb[np][1], Bb[np][3]);
                }
            #pragma unroll
            for (int np = 0; np < 2; np++) {
                uint32_t bd = base + MOFF_BL + SWZ128((uint32_t)((wn*32 + np*16 + rl)*128 + kg*16));
                LDSM4(Bb[np][0], Bb[np][1], Bb[np][2], Bb[np][3], bd);
            }
            #pragma unroll
            for (int mi = 0; mi < 4; mi++)
                #pragma unroll
                for (int np = 0; np < 2; np++) {
                    MMABF(acc[mi][2*np  ], Aa[mi], Bb[np][0], Bb[np][2]);
                    MMABF(acc[mi][2*np+1], Aa[mi], Bb[np][1], Bb[np][3]);
                }
        }
        __syncthreads();
        if (kc + 2 < nkc) load_stage(kc + 2, kc & 1);
    }

    const int mbase = bm*MGM + wm*64 + (lane >> 2);
    const int nbase = bn*MGN + wn*32 + 2*(lane & 3);
    #pragma unroll
    for (int mi = 0; mi < 4; mi++) {
        int r0 = mbase + mi*16, r1 = r0 + 8;
        #pragma unroll
        for (int ni = 0; ni < 4; ni++) {
            int n = nbase + ni*8;
            epi_store<EPI>(acc[mi][ni][0], r0, n,   bias, C, Chi, Clo);
            epi_store<EPI>(acc[mi][ni][1], r0, n+1, bias, C, Chi, Clo);
            epi_store<EPI>(acc[mi][ni][2], r1, n,   bias, C, Chi, Clo);
            epi_store<EPI>(acc[mi][ni][3], r1, n+1, bias, C, Chi, Clo);
        }
    }
}

// ---------------- attention: logits -> softmax -> depend ----------------
__global__ __launch_bounds__(256) void attn_k()
{
    int i = blockIdx.x, b = blockIdx.y;
    size_t r = (size_t)b*SL + i;
    int len = g_caslen[b];
    int jmax = min(i, len);
    int tid = threadIdx.x, w = tid >> 5, l = tid & 31;

    if (jmax == 0) {
        for (int h = tid; h < Hdim; h += 256) {
            g_depend[r*Hdim + h] = 0.f;
            g_dep_hi[r*Hdim + h] = __float2bfloat16(0.f);
            g_dep_lo[r*Hdim + h] = __float2bfloat16(0.f);
        }
        return;
    }

    __shared__ float hrow[Hdim];
    __shared__ float sc[SL];
    __shared__ float red[8];

    for (int h = tid; h < Hdim; h += 256) hrow[h] = g_head[r*Hdim + h];
    __syncthreads();

    for (int j = w; j < jmax; j += 8) {
        const float* trow = g_tail + ((size_t)b*SL + j)*Hdim;
        float s = 0.f;
        #pragma unroll 4
        for (int h = l; h < Hdim; h += 32) s = fmaf(hrow[h], trow[h], s);
        for (int o = 16; o; o >>= 1) s += __shfl_xor_sync(0xffffffffu, s, o);
        if (l == 0) sc[j] = s;
    }
    __syncthreads();

    float m = -1e30f;
    for (int j = tid; j < jmax; j += 256) m = fmaxf(m, sc[j]);
    for (int o = 16; o; o >>= 1) m = fmaxf(m, __shfl_xor_sync(0xffffffffu, m, o));
    if (l == 0) red[w] = m;
    __syncthreads();
    if (tid == 0) { float mm = red[0]; for (int q = 1; q < 8; q++) mm = fmaxf(mm, red[q]); red[0] = mm; }
    __syncthreads();
    m = red[0];

    float ssum = 0.f;
    for (int j = tid; j < jmax; j += 256) { float e = expf(sc[j] - m); sc[j] = e; ssum += e; }
    for (int o = 16; o; o >>= 1) ssum += __shfl_xor_sync(0xffffffffu, ssum, o);
    __syncthreads();
    if (l == 0) red[w] = ssum;
    __syncthreads();
    if (tid == 0) { float t = 0.f; for (int q = 0; q < 8; q++) t += red[q]; red[0] = t; }
    __syncthreads();
    float inv = 1.f / red[0];

    for (int h = tid; h < Hdim; h += 256) {
        float acc = 0.f;
        const float* hp = g_hidden + (size_t)b*SL*Hdim + h;
        for (int j = 0; j < jmax; j++) acc = fmaf(sc[j], hp[(size_t)j*Hdim], acc);
        float dv = acc * inv;
        g_depend[r*Hdim + h] = dv;
        __nv_bfloat16 hh = __float2bfloat16(dv);
        g_dep_hi[r*Hdim + h] = hh;
        g_dep_lo[r*Hdim + h] = __float2bfloat16(dv - __bfloat162float(hh));
    }
}

// ---------------- pool: map2 dot, masked softmax, a16 = pool*enc (fp16) --
__global__ __launch_bounds__(256) void pool_k(
    const float* __restrict__ wm2, const float* __restrict__ bm2)
{
    int b = blockIdx.x, tid = threadIdx.x, w = tid >> 5, l = tid & 31;
    __shared__ float m2[SL];
    __shared__ float red[8];
    int len = g_caslen[b];

    for (int i = w; i < SL; i += 8) {
        size_t r = (size_t)b*SL + i;
        float s = 0.f;
        #pragma unroll 4
        for (int h = l; h < Hdim; h += 32)
            s = fmaf(g_map1[r*Hdim + h] * g_ti[r*Hdim + h], wm2[h], s);
        for (int o = 16; o; o >>= 1) s += __shfl_xor_sync(0xffffffffu, s, o);
        if (l == 0) m2[i] = s + bm2[0];
    }
    __syncthreads();

    float mx = -1e30f;
    for (int i = tid; i < len; i += 256) mx = fmaxf(mx, m2[i]);
    for (int o = 16; o; o >>= 1) mx = fmaxf(mx, __shfl_xor_sync(0xffffffffu, mx, o));
    if (l == 0) red[w] = mx;
    __syncthreads();
    if (tid == 0) { float mm = red[0]; for (int q = 1; q < 8; q++) mm = fmaxf(mm, red[q]); red[0] = mm; }
    __syncthreads();
    mx = red[0];

    float sum = 0.f;
    for (int i = tid; i < len; i += 256) { float e = expf(m2[i] - mx); m2[i] = e; sum += e; }
    for (int o = 16; o; o >>= 1) sum += __shfl_xor_sync(0xffffffffu, sum, o);
    __syncthreads();
    if (l == 0) red[w] = sum;
    __syncthreads();
    if (tid == 0) { float t = 0.f; for (int q = 0; q < 8; q++) t += red[q]; red[0] = t; }
    __syncthreads();
    float inv = (len > 0) ? 1.f / red[0] : 0.f;

    for (int i = tid; i < SL; i += 256) m2[i] = (i < len) ? m2[i]*inv : 0.f;
    __syncthreads();

    size_t base = (size_t)b*SL*Hdim;
    for (int e = tid; e < SL*Hdim; e += 256) {
        int i = e >> 9;
        g_a16[base + e] = __float2half(m2[i] * g_enc[base + e]);
    }
}

// ---------------- final fp16 1-term GEMM ---------------------------------
// C[6400, 32000] = a16[M,512] @ w16[V,512]^T + bias. tile 128x128, KC=64.
#define FSTG 32768
#define SMEM_FG (2*FSTG)   // 65536

__device__ __forceinline__ void load_fin(uint32_t base, const __half* A, const __half* W, int tid){
    #pragma unroll
    for (int t = 0; t < 4; t++) {
        int G = tid + t*256; int r = G >> 3, g = G & 7;
        uint32_t d = SWZ128((uint32_t)(r*128 + g*16));
        cpa16(base + d,         A + (size_t)r*Hdim + g*8);
        cpa16(base + 16384 + d, W + (size_t)r*Hdim + g*8);
    }
    asm volatile("cp.async.commit_group;" ::: "memory");
}

__global__ __launch_bounds__(256, 2) void fgemm_k(
    const float* __restrict__ bias, float* __restrict__ C)
{
    extern __shared__ char smem[];
    const int tid = threadIdx.x, lane = tid & 31, wid = tid >> 5;
    const int bn = blockIdx.x, bm = blockIdx.y;
    const int wm = wid & 1, wn = wid >> 1;     // 2x4 warps, each 64x32
    const int rl = lane & 15, gl = lane >> 4;
    uint32_t sb = smem_u32(smem);

    float acc[4][4][4];
    #pragma unroll
    for (int mi = 0; mi < 4; mi++)
        #pragma unroll
        for (int ni = 0; ni < 4; ni++)
            #pragma unroll
            for (int q = 0; q < 4; q++) acc[mi][ni][q] = 0.f;

    const __half* A0 = g_a16 + (size_t)(bm*128)*Hdim;
    const __half* W0 = g_w16 + (size_t)(bn*128)*Hdim;

    load_fin(sb,        A0,      W0,      tid);
    load_fin(sb + FSTG, A0 + 64, W0 + 64, tid);

    for (int kc = 0; kc < 8; kc++) {
        if (kc < 7) asm volatile("cp.async.wait_group 1;" ::: "memory");
        else        asm volatile("cp.async.wait_group 0;" ::: "memory");
        __syncthreads();
        const uint32_t base = sb + (kc & 1)*FSTG;
        #pragma unroll
        for (int ks = 0; ks < 4; ks++) {
            const int kg = 2*ks + gl;
            uint32_t Aa[4][4], Bb[2][4];
            #pragma unroll
            for (int mi = 0; mi < 4; mi++) {
                uint32_t ad = base + SWZ128((uint32_t)((wm*64 + mi*16 + rl)*128 + kg*16));
                LDSM4(Aa[mi][0], Aa[mi][1], Aa[mi][2], Aa[mi][3], ad);
            }
            #pragma unroll
            for (int np = 0; np < 2; np++) {
                uint32_t bd = base + 16384 + SWZ128((uint32_t)((wn*32 + np*16 + rl)*128 + kg*16));
                LDSM4(Bb[np][0], Bb[np][1], Bb[np][2], Bb[np][3], bd);
            }
            #pragma unroll
            for (int mi = 0; mi < 4; mi++)
                #pragma unroll
                for (int np = 0; np < 2; np++) {
                    MMAFP(acc[mi][2*np  ], Aa[mi], Bb[np][0], Bb[np][2]);
                    MMAFP(acc[mi][2*np+1], Aa[mi], Bb[np][1], Bb[np][3]);
                }
        }
        __syncthreads();
        if (kc + 2 < 8) load_fin(sb + (kc & 1)*FSTG, A0 + (kc+2)*64, W0 + (kc+2)*64, tid);
    }

    const int m0 = bm*128 + wm*64 + (lane >> 2);
    const int n0 = bn*128 + wn*32 + 2*(lane & 3);
    #pragma unroll
    for (int mi = 0; mi < 4; mi++) {
        int m = m0 + mi*16;
        #pragma unroll
        for (int ni = 0; ni < 4; ni++) {
            int n = n0 + ni*8;
            float b0 = bias[n], b1 = bias[n+1];
            float2 v0 = make_float2(acc[mi][ni][0] + b0, acc[mi][ni][1] + b1);
            float2 v1 = make_float2(acc[mi][ni][2] + b0, acc[mi][ni][3] + b1);
            *(float2*)(C + (size_t)m*Vdim + n)     = v0;
            *(float2*)(C + (size_t)(m+8)*Vdim + n) = v1;
        }
    }
}

// ---------------- launch ------------------------------------------------
extern "C" void kernel_launch(void* const* d_in, const int* in_sizes, int n_in,
                              void* d_out, int out_size)
{
    const int*   cas  = (const int*)  d_in[0];
    const int*   tii  = (const int*)  d_in[1];
    const float* emb  = (const float*)d_in[2];
    const float* tlam = (const float*)d_in[3];
    const float* w1   = (const float*)d_in[4];
    const float* b1   = (const float*)d_in[5];
    const float* wh   = (const float*)d_in[6];
    const float* bh   = (const float*)d_in[7];
    const float* wt   = (const float*)d_in[8];
    const float* bt   = (const float*)d_in[9];
    const float* wg   = (const float*)d_in[10];
    const float* bg   = (const float*)d_in[11];
    const float* wm1  = (const float*)d_in[12];
    const float* bm1  = (const float*)d_in[13];
    const float* wti  = (const float*)d_in[14];
    const float* bti  = (const float*)d_in[15];
    const float* wm2  = (const float*)d_in[16];
    const float* bm2  = (const float*)d_in[17];
    const float* wout = (const float*)d_in[18];
    const float* bout = (const float*)d_in[19];
    float* out = (float*)d_out;

    // symbol addresses
    float *p_hidden, *p_head, *p_tail, *p_map1, *p_ti, *p_enc;
    __nv_bfloat16 *p_emb_h, *p_emb_l, *p_tw_h, *p_tw_l, *p_hid_h, *p_hid_l;
    __nv_bfloat16 *p_dep_h, *p_dep_l, *p_enc_h, *p_enc_l;
    __nv_bfloat16 *p_w1h, *p_w1l, *p_whh, *p_whl, *p_wth, *p_wtl;
    __nv_bfloat16 *p_wm1h, *p_wm1l, *p_wtih, *p_wtil, *p_wgh, *p_wgl;
    __half *p_w16;
    cudaGetSymbolAddress((void**)&p_hidden, g_hidden);
    cudaGetSymbolAddress((void**)&p_head,   g_head);
    cudaGetSymbolAddress((void**)&p_tail,   g_tail);
    cudaGetSymbolAddress((void**)&p_map1,   g_map1);
    cudaGetSymbolAddress((void**)&p_ti,     g_ti);
    cudaGetSymbolAddress((void**)&p_enc,    g_enc);
    cudaGetSymbolAddress((void**)&p_emb_h,  g_emb_hi);
    cudaGetSymbolAddress((void**)&p_emb_l,  g_emb_lo);
    cudaGetSymbolAddress((void**)&p_tw_h,   g_tw_hi);
    cudaGetSymbolAddress((void**)&p_tw_l,   g_tw_lo);
    cudaGetSymbolAddress((void**)&p_hid_h,  g_hid_hi);
    cudaGetSymbolAddress((void**)&p_hid_l,  g_hid_lo);
    cudaGetSymbolAddress((void**)&p_dep_h,  g_dep_hi);
    cudaGetSymbolAddress((void**)&p_dep_l,  g_dep_lo);
    cudaGetSymbolAddress((void**)&p_enc_h,  g_enc_hi);
    cudaGetSymbolAddress((void**)&p_enc_l,  g_enc_lo);
    cudaGetSymbolAddress((void**)&p_w1h,    g_w1T_h);
    cudaGetSymbolAddress((void**)&p_w1l,    g_w1T_l);
    cudaGetSymbolAddress((void**)&p_whh,    g_whT_h);
    cudaGetSymbolAddress((void**)&p_whl,    g_whT_l);
    cudaGetSymbolAddress((void**)&p_wth,    g_wtT_h);
    cudaGetSymbolAddress((void**)&p_wtl,    g_wtT_l);
    cudaGetSymbolAddress((void**)&p_wm1h,   g_wm1T_h);
    cudaGetSymbolAddress((void**)&p_wm1l,   g_wm1T_l);
    cudaGetSymbolAddress((void**)&p_wtih,   g_wtiT_h);
    cudaGetSymbolAddress((void**)&p_wtil,   g_wtiT_l);
    cudaGetSymbolAddress((void**)&p_wgh,    g_wgT_h);
    cudaGetSymbolAddress((void**)&p_wgl,    g_wgT_l);
    cudaGetSymbolAddress((void**)&p_w16,    g_w16);

    cudaFuncSetAttribute(mgemm_k<0>, cudaFuncAttributeMaxDynamicSharedMemorySize, SMEM_MG);
    cudaFuncSetAttribute(mgemm_k<1>, cudaFuncAttributeMaxDynamicSharedMemorySize, SMEM_MG);
    cudaFuncSetAttribute(mgemm_k<2>, cudaFuncAttributeMaxDynamicSharedMemorySize, SMEM_MG);
    cudaFuncSetAttribute(mgemm_k<3>, cudaFuncAttributeMaxDynamicSharedMemorySize, SMEM_MG);
    cudaFuncSetAttribute(fgemm_k,    cudaFuncAttributeMaxDynamicSharedMemorySize, SMEM_FG);

    caslen_k<<<Bc, 256>>>(cas);

    // weight preprocessing (independent of activations)
    transW_f16_k<<<dim3(Vdim/32, Hdim/32), dim3(32,8)>>>(wout, p_w16);
    transW_bf16_k<<<dim3(16,16), dim3(32,8)>>>(w1,  p_w1h,  p_w1l,  Hdim);
    transW_bf16_k<<<dim3(16,16), dim3(32,8)>>>(wh,  p_whh,  p_whl,  Hdim);
    transW_bf16_k<<<dim3(16,16), dim3(32,8)>>>(wt,  p_wth,  p_wtl,  Hdim);
    transW_bf16_k<<<dim3(16,16), dim3(32,8)>>>(wm1, p_wm1h, p_wm1l, Hdim);
    transW_bf16_k<<<dim3(16,16), dim3(32,8)>>>(wti, p_wtih, p_wtil, Hdim);
    transW_bf16_k<<<dim3(16,32), dim3(32,8)>>>(wg,  p_wgh,  p_wgl,  2*Hdim);

    // activation gathers + splits
    gatherSplit_k<<<(Mrows*Hdim)/256, 256>>>(emb,  cas, p_emb_h, p_emb_l);
    gatherSplit_k<<<(Mrows*Hdim)/256, 256>>>(tlam, tii, p_tw_h,  p_tw_l);

    dim3 gmid(Hdim/MGN, Mrows/MGM);    // (4, 50)
    // hidden = elu(emb@w1+b1)*mask  (+ bf16 splits)
    mgemm_k<1><<<gmid, 256, SMEM_MG>>>(p_emb_h, p_emb_l, p_emb_h, p_emb_l,
                                       p_w1h, p_w1l, Hdim, 8, b1,
                                       p_hidden, p_hid_h, p_hid_l);
    // head / tail
    mgemm_k<0><<<gmid, 256, SMEM_MG>>>(p_hid_h, p_hid_l, p_hid_h, p_hid_l,
                                       p_whh, p_whl, Hdim, 8, bh,
                                       p_head, nullptr, nullptr);
    mgemm_k<0><<<gmid, 256, SMEM_MG>>>(p_hid_h, p_hid_l, p_hid_h, p_hid_l,
                                       p_wth, p_wtl, Hdim, 8, bt,
                                       p_tail, nullptr, nullptr);
    // attention -> depend (+ splits)
    attn_k<<<dim3(SL, Bc), 256>>>();
    // gate: sigmoid([hidden|depend]@wg+bg) combine -> enc (+ splits)
    mgemm_k<3><<<gmid, 256, SMEM_MG>>>(p_hid_h, p_hid_l, p_dep_h, p_dep_l,
                                       p_wgh, p_wgl, 2*Hdim, 16, bg,
                                       p_enc, p_enc_h, p_enc_l);
    // map1 = elu(enc@wm1+bm1); ti = elu(tw@wti+bti)
    mgemm_k<2><<<gmid, 256, SMEM_MG>>>(p_enc_h, p_enc_l, p_enc_h, p_enc_l,
                                       p_wm1h, p_wm1l, Hdim, 8, bm1,
                                       p_map1, nullptr, nullptr);
    mgemm_k<2><<<gmid, 256, SMEM_MG>>>(p_tw_h, p_tw_l, p_tw_h, p_tw_l,
                                       p_wtih, p_wtil, Hdim, 8, bti,
                                       p_ti, nullptr, nullptr);
    // pool -> a16 (fp16)
    pool_k<<<Bc, 256>>>(wm2, bm2);
    // final: out = a16 @ w16^T + bout  (fp16 single product)
    fgemm_k<<<dim3(Vdim/128, Mrows/128), 256, SMEM_FG>>>(bout, out);
}

// round 9
// speedup vs baseline: 3.9855x; 1.0595x over previous
#include <cuda_runtime.h>
#include <cuda_bf16.h>
#include <cuda_fp16.h>
#include <math.h>
#include <stdint.h>

#define Bc   32
#define Ssz  201
#define SL   200
#define Hdim 512
#define Vdim 32000
#define Mrows (Bc*SL)   // 6400

// ---------------- scratch (static device globals; no allocation) ------------
__device__ __align__(16) float g_hidden[Mrows*Hdim];
__device__ __align__(16) float g_depend[Mrows*Hdim];
__device__ __align__(16) float g_enc   [Mrows*Hdim];
__device__ __align__(16) float g_map1  [Mrows*Hdim];
__device__ __align__(16) float g_ti    [Mrows*Hdim];
__device__ int g_caslen[Bc];

// bf16 split activations (hi/lo)
__device__ __align__(16) __nv_bfloat16 g_emb_hi[Mrows*Hdim];
__device__ __align__(16) __nv_bfloat16 g_emb_lo[Mrows*Hdim];
__device__ __align__(16) __nv_bfloat16 g_tw_hi [Mrows*Hdim];
__device__ __align__(16) __nv_bfloat16 g_tw_lo [Mrows*Hdim];
__device__ __align__(16) __nv_bfloat16 g_hid_hi[Mrows*Hdim];
__device__ __align__(16) __nv_bfloat16 g_hid_lo[Mrows*Hdim];
__device__ __align__(16) __nv_bfloat16 g_hed_hi[Mrows*Hdim];
__device__ __align__(16) __nv_bfloat16 g_hed_lo[Mrows*Hdim];
__device__ __align__(16) __nv_bfloat16 g_tal_hi[Mrows*Hdim];
__device__ __align__(16) __nv_bfloat16 g_tal_lo[Mrows*Hdim];
__device__ __align__(16) __nv_bfloat16 g_dep_hi[Mrows*Hdim];
__device__ __align__(16) __nv_bfloat16 g_dep_lo[Mrows*Hdim];
__device__ __align__(16) __nv_bfloat16 g_enc_hi[Mrows*Hdim];
__device__ __align__(16) __nv_bfloat16 g_enc_lo[Mrows*Hdim];

// hidden transposed per batch: [b][h][jpad=256] (zero-init covers j>=224 pad)
__device__ __align__(16) __nv_bfloat16 g_hidT_h[Bc*Hdim*256];
__device__ __align__(16) __nv_bfloat16 g_hidT_l[Bc*Hdim*256];

// bf16 split transposed weights [N, K] K-major
__device__ __align__(16) __nv_bfloat16 g_w1T_h [Hdim*Hdim];
__device__ __align__(16) __nv_bfloat16 g_w1T_l [Hdim*Hdim];
__device__ __align__(16) __nv_bfloat16 g_whT_h [Hdim*Hdim];
__device__ __align__(16) __nv_bfloat16 g_whT_l [Hdim*Hdim];
__device__ __align__(16) __nv_bfloat16 g_wtT_h [Hdim*Hdim];
__device__ __align__(16) __nv_bfloat16 g_wtT_l [Hdim*Hdim];
__device__ __align__(16) __nv_bfloat16 g_wm1T_h[Hdim*Hdim];
__device__ __align__(16) __nv_bfloat16 g_wm1T_l[Hdim*Hdim];
__device__ __align__(16) __nv_bfloat16 g_wtiT_h[Hdim*Hdim];
__device__ __align__(16) __nv_bfloat16 g_wtiT_l[Hdim*Hdim];
__device__ __align__(16) __nv_bfloat16 g_wgT_h [Hdim*2*Hdim];
__device__ __align__(16) __nv_bfloat16 g_wgT_l [Hdim*2*Hdim];

// fp16 operands for the final 1-term GEMM
__device__ __align__(16) __half g_a16[Mrows*Hdim];
__device__ __align__(16) __half g_w16[(size_t)Vdim*Hdim];   // [V, H] K-major

__device__ __forceinline__ float elu_f(float x){ return x > 0.f ? x : (expf(x) - 1.f); }

// ========================= mma helpers =====================================
__device__ __forceinline__ uint32_t smem_u32(const void* p){
    uint32_t a;
    asm("{ .reg .u64 t; cvta.to.shared.u64 t, %1; cvt.u32.u64 %0, t; }" : "=r"(a) : "l"(p));
    return a;
}
#define SWZ128(off) ((off) ^ (((off) >> 3) & 0x70))

__device__ __forceinline__ void cpa16(uint32_t s, const void* g){
    asm volatile("cp.async.cg.shared.global [%0], [%1], 16;" :: "r"(s), "l"(g));
}

#define LDSM4(r0, r1, r2, r3, addr) \
    asm volatile("ldmatrix.sync.aligned.m8n8.x4.shared.b16 {%0,%1,%2,%3}, [%4];" \
        : "=r"(r0), "=r"(r1), "=r"(r2), "=r"(r3) : "r"(addr))

#define MMABF(c, a, b0, b1) \
    asm volatile("mma.sync.aligned.m16n8k16.row.col.f32.bf16.bf16.f32 " \
        "{%0,%1,%2,%3},{%4,%5,%6,%7},{%8,%9},{%0,%1,%2,%3};" \
        : "+f"((c)[0]), "+f"((c)[1]), "+f"((c)[2]), "+f"((c)[3]) \
        : "r"((a)[0]), "r"((a)[1]), "r"((a)[2]), "r"((a)[3]), "r"(b0), "r"(b1))

#define MMAFP(c, a, b0, b1) \
    asm volatile("mma.sync.aligned.m16n8k16.row.col.f32.f16.f16.f32 " \
        "{%0,%1,%2,%3},{%4,%5,%6,%7},{%8,%9},{%0,%1,%2,%3};" \
        : "+f"((c)[0]), "+f"((c)[1]), "+f"((c)[2]), "+f"((c)[3]) \
        : "r"((a)[0]), "r"((a)[1]), "r"((a)[2]), "r"((a)[3]), "r"(b0), "r"(b1))

// ---------------- cas_len -----------------------------------------------
__global__ void caslen_k(const int* __restrict__ cas){
    int b = blockIdx.x, tid = threadIdx.x;
    int c = (tid < SL && cas[b*Ssz + tid] != 0) ? 1 : 0;
    for (int o = 16; o; o >>= 1) c += __shfl_xor_sync(0xffffffffu, c, o);
    __shared__ int s[8];
    if ((tid & 31) == 0) s[tid >> 5] = c;
    __syncthreads();
    if (tid == 0) { int t = 0; for (int q = 0; q < 8; q++) t += s[q]; g_caslen[b] = t; }
}

// ---------------- weight transpose + split -------------------------------
__global__ void transW_bf16_k(const float* __restrict__ w,
                              __nv_bfloat16* __restrict__ hi,
                              __nv_bfloat16* __restrict__ lo, int Kdim){
    __shared__ float t[32][33];
    int n0 = blockIdx.x*32, k0 = blockIdx.y*32;
    int x = threadIdx.x, y = threadIdx.y;
    for (int i = y; i < 32; i += 8)
        t[i][x] = w[(size_t)(k0+i)*Hdim + n0 + x];
    __syncthreads();
    for (int nn = y; nn < 32; nn += 8) {
        float v = t[x][nn];
        __nv_bfloat16 h = __float2bfloat16(v);
        size_t o = (size_t)(n0+nn)*Kdim + k0 + x;
        hi[o] = h;
        lo[o] = __float2bfloat16(v - __bfloat162float(h));
    }
}

__global__ void transW_f16_k(const float* __restrict__ w, __half* __restrict__ out){
    __shared__ float t[32][33];
    int n0 = blockIdx.x*32, k0 = blockIdx.y*32;
    int x = threadIdx.x, y = threadIdx.y;
    for (int i = y; i < 32; i += 8)
        t[i][x] = w[(size_t)(k0+i)*Vdim + n0 + x];
    __syncthreads();
    for (int nn = y; nn < 32; nn += 8)
        out[(size_t)(n0+nn)*Hdim + k0 + x] = __float2half(t[x][nn]);
}

__global__ void gatherSplit_k(const float* __restrict__ table, const int* __restrict__ idx,
                              __nv_bfloat16* __restrict__ hi, __nv_bfloat16* __restrict__ lo){
    int i = blockIdx.x*256 + threadIdx.x;
    int r = i >> 9, c = i & 511;
    int row = idx[(r/SL)*Ssz + (r%SL)];
    float v = table[(size_t)row*Hdim + c];
    __nv_bfloat16 h = __float2bfloat16(v);
    hi[i] = h;
    lo[i] = __float2bfloat16(v - __bfloat162float(h));
}

// hidden [b*SL+j][h] -> hidT hi/lo [b][h][256]   (j pad 224..255 stays zero)
__global__ void transHid_k(){
    __shared__ float t[32][33];
    int b = blockIdx.z;
    int j0 = blockIdx.x*32, h0 = blockIdx.y*32;
    int x = threadIdx.x, y = threadIdx.y;  // (32, 8)
    for (int i = y; i < 32; i += 8) {
        int j = j0 + i;
        t[i][x] = (j < SL) ? g_hidden[(size_t)(b*SL + j)*Hdim + h0 + x] : 0.f;
    }
    __syncthreads();
    for (int hh = y; hh < 32; hh += 8) {
        float v = t[x][hh];
        __nv_bfloat16 h = __float2bfloat16(v);
        size_t o = ((size_t)(b*Hdim + h0 + hh))*256 + j0 + x;
        g_hidT_h[o] = h;
        g_hidT_l[o] = __float2bfloat16(v - __bfloat162float(h));
    }
}

// ---------------- mid bf16 3-term mma GEMM -------------------------------
#define MGM 128
#define MGN 128
#define MKC 64
#define MOFF_AH 0
#define MOFF_AL 16384
#define MOFF_BH 32768
#define MOFF_BL 49152
#define MSTG 65536
#define SMEM_MG (2*MSTG)   // 131072

// EPI: 0 bias; 1 bias+elu+mask+splits; 2 bias+elu; 3 gate-combine+mask+splits; 4 bias+splits only
template<int EPI>
__device__ __forceinline__ void epi_store(float v, int r, int c,
    const float* __restrict__ bias, float* __restrict__ C,
    __nv_bfloat16* __restrict__ Chi, __nv_bfloat16* __restrict__ Clo)
{
    v += bias[c];
    if (EPI == 1 || EPI == 2) v = elu_f(v);
    if (EPI == 3) {
        float g = 1.f / (1.f + expf(-v));
        float h = g_hidden[(size_t)r*Hdim + c];
        float d = g_depend[(size_t)r*Hdim + c];
        v = g*h + (1.f - g)*d;
    }
    if (EPI == 1 || EPI == 3) {
        int bb = r / SL, ii = r % SL;
        if (ii >= g_caslen[bb]) v = 0.f;
    }
    if (EPI != 4) C[(size_t)r*Hdim + c] = v;
    if (EPI == 1 || EPI == 3 || EPI == 4) {
        __nv_bfloat16 h = __float2bfloat16(v);
        Chi[(size_t)r*Hdim + c] = h;
        Clo[(size_t)r*Hdim + c] = __float2bfloat16(v - __bfloat162float(h));
    }
}

template<int EPI>
__global__ __launch_bounds__(256) void mgemm_k(
    const __nv_bfloat16* __restrict__ Ah0, const __nv_bfloat16* __restrict__ Al0,
    const __nv_bfloat16* __restrict__ Ah1, const __nv_bfloat16* __restrict__ Al1,
    const __nv_bfloat16* __restrict__ Wh,  const __nv_bfloat16* __restrict__ Wl,
    int ldw, int nkc,
    const float* __restrict__ bias, float* __restrict__ C,
    __nv_bfloat16* __restrict__ Chi, __nv_bfloat16* __restrict__ Clo)
{
    extern __shared__ char smem[];
    const int tid = threadIdx.x, lane = tid & 31, wid = tid >> 5;
    const int bn = blockIdx.x, bm = blockIdx.y;
    const int wm = wid & 1, wn = wid >> 1;
    const int rl = lane & 15, gl = lane >> 4;
    uint32_t sb = smem_u32(smem);

    float acc[4][4][4];
    #pragma unroll
    for (int mi = 0; mi < 4; mi++)
        #pragma unroll
        for (int ni = 0; ni < 4; ni++)
            #pragma unroll
            for (int q = 0; q < 4; q++) acc[mi][ni][q] = 0.f;

    auto load_stage = [&](int kc, int buf){
        const __nv_bfloat16 *ah, *al; int koff;
        if (kc < 8) { ah = Ah0; al = Al0; koff = kc*MKC; }
        else        { ah = Ah1; al = Al1; koff = (kc-8)*MKC; }
        const __nv_bfloat16* ap_h = ah + (size_t)(bm*MGM)*Hdim + koff;
        const __nv_bfloat16* ap_l = al + (size_t)(bm*MGM)*Hdim + koff;
        const __nv_bfloat16* wp_h = Wh + (size_t)(bn*MGN)*ldw + kc*MKC;
        const __nv_bfloat16* wp_l = Wl + (size_t)(bn*MGN)*ldw + kc*MKC;
        uint32_t base = sb + buf*MSTG;
        #pragma unroll
        for (int t = 0; t < 4; t++) {
            int G = tid + t*256; int r = G >> 3, g = G & 7;
            uint32_t d = SWZ128((uint32_t)(r*128 + g*16));
            cpa16(base + MOFF_AH + d, ap_h + (size_t)r*Hdim + g*8);
            cpa16(base + MOFF_AL + d, ap_l + (size_t)r*Hdim + g*8);
            cpa16(base + MOFF_BH + d, wp_h + (size_t)r*ldw + g*8);
            cpa16(base + MOFF_BL + d, wp_l + (size_t)r*ldw + g*8);
        }
        asm volatile("cp.async.commit_group;" ::: "memory");
    };

    load_stage(0, 0);
    load_stage(1, 1);

    for (int kc = 0; kc < nkc; kc++) {
        if (kc < nkc-1) asm volatile("cp.async.wait_group 1;" ::: "memory");
        else            asm volatile("cp.async.wait_group 0;" ::: "memory");
        __syncthreads();
        const uint32_t base = sb + (kc & 1)*MSTG;
        #pragma unroll
        for (int ks = 0; ks < 4; ks++) {
            const int kg = 2*ks + gl;
            uint32_t Aa[4][4], Bb[2][4], Al2[4][4];
            #pragma unroll
            for (int mi = 0; mi < 4; mi++) {
                uint32_t ad = base + MOFF_AH + SWZ128((uint32_t)((wm*64 + mi*16 + rl)*128 + kg*16));
                LDSM4(Aa[mi][0], Aa[mi][1], Aa[mi][2], Aa[mi][3], ad);
            }
            #pragma unroll
            for (int np = 0; np < 2; np++) {
                uint32_t bd = base + MOFF_BH + SWZ128((uint32_t)((wn*32 + np*16 + rl)*128 + kg*16));
                LDSM4(Bb[np][0], Bb[np][1], Bb[np][2], Bb[np][3], bd);
            }
            #pragma unroll
            for (int mi = 0; mi < 4; mi++)
                #pragma unroll
                for (int np = 0; np < 2; np++) {
                    MMABF(acc[mi][2*np  ], Aa[mi], Bb[np][0], Bb[np][2]);
                    MMABF(acc[mi][2*np+1], Aa[mi], Bb[np][1], Bb[np][3]);
                }
            #pragma unroll
            for (int mi = 0; mi < 4; mi++) {
                uint32_t ad = base + MOFF_AL + SWZ128((uint32_t)((wm*64 + mi*16 + rl)*128 + kg*16));
                LDSM4(Al2[mi][0], Al2[mi][1], Al2[mi][2], Al2[mi][3], ad);
            }
            #pragma unroll
            for (int mi = 0; mi < 4; mi++)
                #pragma unroll
                for (int np = 0; np < 2; np++) {
                    MMABF(acc[mi][2*np  ], Al2[mi], Bb[np][0], Bb[np][2]);
                    MMABF(acc[mi][2*np+1], Al2[mi], Bb[np][1], Bb[np][3]);
                }
            #pragma unroll
            for (int np = 0; np < 2; np++) {
                uint32_t bd = base + MOFF_BL + SWZ128((uint32_t)((wn*32 + np*16 + rl)*128 + kg*16));
                LDSM4(Bb[np][0], Bb[np][1], Bb[np][2], Bb[np][3], bd);
            }
            #pragma unroll
            for (int mi = 0; mi < 4; mi++)
                #pragma unroll
                for (int np = 0; np < 2; np++) {
                    MMABF(acc[mi][2*np  ], Aa[mi], Bb[np][0], Bb[np][2]);
                    MMABF(acc[mi][2*np+1], Aa[mi], Bb[np][1], Bb[np][3]);
                }
        }
        __syncthreads();
        if (kc + 2 < nkc) load_stage(kc + 2, kc & 1);
    }

    const int mbase = bm*MGM + wm*64 + (lane >> 2);
    const int nbase = bn*MGN + wn*32 + 2*(lane & 3);
    #pragma unroll
    for (int mi = 0; mi < 4; mi++) {
        int r0 = mbase + mi*16, r1 = r0 + 8;
        #pragma unroll
        for (int ni = 0; ni < 4; ni++) {
            int n = nbase + ni*8;
            epi_store<EPI>(acc[mi][ni][0], r0, n,   bias, C, Chi, Clo);
            epi_store<EPI>(acc[mi][ni][1], r0, n+1, bias, C, Chi, Clo);
            epi_store<EPI>(acc[mi][ni][2], r1, n,   bias, C, Chi, Clo);
            epi_store<EPI>(acc[mi][ni][3], r1, n+1, bias, C, Chi, Clo);
        }
    }
}

// ---------------- attention via mma --------------------------------------
// Per block: b = blockIdx.y, t = blockIdx.x (i-tile of 64).
// GEMM1: logits[64][256] = head_tile @ tail^T (3-term bf16 split)
// masked softmax -> score hi/lo in smem chunks [4][64][64]
// GEMM2: depend[64][512] = score @ hidden (via hidT [h][j], 3-term)
#define AT_S_HI 0
#define AT_S_LO 32768
#define AT_STG  65536
// GEMM1 stage: headH +0 (8K), headL +8192, tailH +16384 (32K), tailL +49152 -> 80K
// GEMM2 stage: hidH +0 (64K), hidL +65536 -> 128K
#define AT_RED  (AT_STG + 131072)   // 196608, 2KB floats
#define SMEM_AT (196608 + 2048)     // 198656

__global__ __launch_bounds__(256) void attnmma_k()
{
    extern __shared__ char smem[];
    const int tid = threadIdx.x, lane = tid & 31, wid = tid >> 5;
    const int t = blockIdx.x, b = blockIdx.y;
    const int len = g_caslen[b];
    const int rl = lane & 15, gl = lane >> 4;
    uint32_t sb = smem_u32(smem);
    const uint32_t stg = sb + AT_STG;
    float* red = (float*)(smem + AT_RED);   // [64][8]

    // ---------- GEMM1: logits ----------
    float acc1[4][4][4];
    #pragma unroll
    for (int mi = 0; mi < 4; mi++)
        #pragma unroll
        for (int ni = 0; ni < 4; ni++)
            #pragma unroll
            for (int q = 0; q < 4; q++) acc1[mi][ni][q] = 0.f;

    for (int kc = 0; kc < 8; kc++) {
        // load head chunk (64 rows) + tail chunk (256 rows), hi/lo
        #pragma unroll
        for (int q = 0; q < 2; q++) {
            int G = tid + q*256; int r = G >> 3, g = G & 7;
            int gi = t*64 + r; if (gi >= SL) gi = SL-1;
            size_t go = (size_t)(b*SL + gi)*Hdim + kc*64 + g*8;
            uint32_t d = SWZ128((uint32_t)(r*128 + g*16));
            cpa16(stg + 0    + d, g_hed_hi + go);
            cpa16(stg + 8192 + d, g_hed_lo + go);
        }
        #pragma unroll
        for (int q = 0; q < 8; q++) {
            int G = tid + q*256; int r = G >> 3, g = G & 7;
            int gj = (r < SL) ? r : SL-1;
            size_t go = (size_t)(b*SL + gj)*Hdim + kc*64 + g*8;
            uint32_t d = SWZ128((uint32_t)(r*128 + g*16));
            cpa16(stg + 16384 + d, g_tal_hi + go);
            cpa16(stg + 49152 + d, g_tal_lo + go);
        }
        asm volatile("cp.async.commit_group;" ::: "memory");
        asm volatile("cp.async.wait_group 0;" ::: "memory");
        __syncthreads();

        #pragma unroll
        for (int ks = 0; ks < 4; ks++) {
            const int kg = 2*ks + gl;
            uint32_t Aa[4][4], Bb[2][4], Al2[4][4];
            #pragma unroll
            for (int mi = 0; mi < 4; mi++) {
                uint32_t ad = stg + 0 + SWZ128((uint32_t)((mi*16 + rl)*128 + kg*16));
                LDSM4(Aa[mi][0], Aa[mi][1], Aa[mi][2], Aa[mi][3], ad);
            }
            #pragma unroll
            for (int np = 0; np < 2; np++) {
                uint32_t bd = stg + 16384 + SWZ128((uint32_t)((wid*32 + np*16 + rl)*128 + kg*16));
                LDSM4(Bb[np][0], Bb[np][1], Bb[np][2], Bb[np][3], bd);
            }
            #pragma unroll
            for (int mi = 0; mi < 4; mi++)
                #pragma unroll
                for (int np = 0; np < 2; np++) {
                    MMABF(acc1[mi][2*np  ], Aa[mi], Bb[np][0], Bb[np][2]);
                    MMABF(acc1[mi][2*np+1], Aa[mi], Bb[np][1], Bb[np][3]);
                }
            #pragma unroll
            for (int mi = 0; mi < 4; mi++) {
                uint32_t ad = stg + 8192 + SWZ128((uint32_t)((mi*16 + rl)*128 + kg*16));
                LDSM4(Al2[mi][0], Al2[mi][1], Al2[mi][2], Al2[mi][3], ad);
            }
            #pragma unroll
            for (int mi = 0; mi < 4; mi++)
                #pragma unroll
                for (int np = 0; np < 2; np++) {
                    MMABF(acc1[mi][2*np  ], Al2[mi], Bb[np][0], Bb[np][2]);
                    MMABF(acc1[mi][2*np+1], Al2[mi], Bb[np][1], Bb[np][3]);
                }
            #pragma unroll
            for (int np = 0; np < 2; np++) {
                uint32_t bd = stg + 49152 + SWZ128((uint32_t)((wid*32 + np*16 + rl)*128 + kg*16));
                LDSM4(Bb[np][0], Bb[np][1], Bb[np][2], Bb[np][3], bd);
            }
            #pragma unroll
            for (int mi = 0; mi < 4; mi++)
                #pragma unroll
                for (int np = 0; np < 2; np++) {
                    MMABF(acc1[mi][2*np  ], Aa[mi], Bb[np][0], Bb[np][2]);
                    MMABF(acc1[mi][2*np+1], Aa[mi], Bb[np][1], Bb[np][3]);
                }
        }
        __syncthreads();
    }

    // ---------- masked softmax ----------
    // element: row = mi*16 + (lane>>2) + 8*qh, col j = wid*32 + ni*8 + 2*(lane&3) + q0
    const int rbase = lane >> 2, cbase = 2*(lane & 3);
    float rmax[4][2];
    #pragma unroll
    for (int mi = 0; mi < 4; mi++)
        #pragma unroll
        for (int qh = 0; qh < 2; qh++) {
            int ig = t*64 + mi*16 + rbase + 8*qh;
            float m = -1e30f;
            #pragma unroll
            for (int ni = 0; ni < 4; ni++)
                #pragma unroll
                for (int q0 = 0; q0 < 2; q0++) {
                    int jg = wid*32 + ni*8 + cbase + q0;
                    float v = acc1[mi][ni][qh*2 + q0];
                    if (jg < ig && jg < len) m = fmaxf(m, v);
                }
            m = fmaxf(m, __shfl_xor_sync(0xffffffffu, m, 1));
            m = fmaxf(m, __shfl_xor_sync(0xffffffffu, m, 2));
            rmax[mi][qh] = m;
            if ((lane & 3) == 0) red[(mi*16 + rbase + 8*qh)*8 + wid] = m;
        }
    __syncthreads();
    #pragma unroll
    for (int mi = 0; mi < 4; mi++)
        #pragma unroll
        for (int qh = 0; qh < 2; qh++) {
            float m = -1e30f;
            int row = mi*16 + rbase + 8*qh;
            #pragma unroll
            for (int w = 0; w < 8; w++) m = fmaxf(m, red[row*8 + w]);
            rmax[mi][qh] = m;
        }
    __syncthreads();   // red reuse

    float rsum[4][2];
    #pragma unroll
    for (int mi = 0; mi < 4; mi++)
        #pragma unroll
        for (int qh = 0; qh < 2; qh++) {
            int ig = t*64 + mi*16 + rbase + 8*qh;
            float s = 0.f;
            #pragma unroll
            for (int ni = 0; ni < 4; ni++)
                #pragma unroll
                for (int q0 = 0; q0 < 2; q0++) {
                    int jg = wid*32 + ni*8 + cbase + q0;
                    float v = acc1[mi][ni][qh*2 + q0];
                    float e = (jg < ig && jg < len) ? expf(v - rmax[mi][qh]) : 0.f;
                    acc1[mi][ni][qh*2 + q0] = e;
                    s += e;
                }
            s += __shfl_xor_sync(0xffffffffu, s, 1);
            s += __shfl_xor_sync(0xffffffffu, s, 2);
            if ((lane & 3) == 0) red[(mi*16 + rbase + 8*qh)*8 + wid] = s;
        }
    __syncthreads();
    #pragma unroll
    for (int mi = 0; mi < 4; mi++)
        #pragma unroll
        for (int qh = 0; qh < 2; qh++) {
            float s = 0.f;
            int row = mi*16 + rbase + 8*qh;
            #pragma unroll
            for (int w = 0; w < 8; w++) s += red[row*8 + w];
            rsum[mi][qh] = (s > 0.f) ? 1.f/s : 0.f;
        }

    // write score hi/lo into smem chunks [4][64][64]
    #pragma unroll
    for (int mi = 0; mi < 4; mi++)
        #pragma unroll
        for (int qh = 0; qh < 2; qh++) {
            int row = mi*16 + rbase + 8*qh;
            #pragma unroll
            for (int ni = 0; ni < 4; ni++)
                #pragma unroll
                for (int q0 = 0; q0 < 2; q0++) {
                    int jg = wid*32 + ni*8 + cbase + q0;
                    float p = acc1[mi][ni][qh*2 + q0] * rsum[mi][qh];
                    __nv_bfloat16 ph = __float2bfloat16(p);
                    __nv_bfloat16 pl = __float2bfloat16(p - __bfloat162float(ph));
                    int chunk = jg >> 6, col = jg & 63;
                    uint32_t off = chunk*8192 + SWZ128((uint32_t)(row*128 + col*2));
                    uint16_t uh = *(uint16_t*)&ph, ul = *(uint16_t*)&pl;
                    asm volatile("st.shared.b16 [%0], %1;" :: "r"(sb + AT_S_HI + off), "h"(uh));
                    asm volatile("st.shared.b16 [%0], %1;" :: "r"(sb + AT_S_LO + off), "h"(ul));
                }
        }
    __syncthreads();

    // ---------- GEMM2: depend = score @ hidden ----------
    float acc2[4][8][4];
    #pragma unroll
    for (int mi = 0; mi < 4; mi++)
        #pragma unroll
        for (int nj = 0; nj < 8; nj++)
            #pragma unroll
            for (int q = 0; q < 4; q++) acc2[mi][nj][q] = 0.f;

    for (int kc = 0; kc < 4; kc++) {
        // load hidT chunk: 512 h-rows x 64 j-cols, hi/lo
        #pragma unroll
        for (int q = 0; q < 16; q++) {
            int G = tid + q*256; int r = G >> 3, g = G & 7;
            size_t go = ((size_t)(b*Hdim + r))*256 + kc*64 + g*8;
            uint32_t d = SWZ128((uint32_t)(r*128 + g*16));
            cpa16(stg + 0     + d, g_hidT_h + go);
            cpa16(stg + 65536 + d, g_hidT_l + go);
        }
        asm volatile("cp.async.commit_group;" ::: "memory");
        asm volatile("cp.async.wait_group 0;" ::: "memory");
        __syncthreads();

        #pragma unroll
        for (int ks = 0; ks < 4; ks++) {
            const int kg = 2*ks + gl;
            uint32_t Aa[4][4], Bb[4][4], Al2[4][4];
            #pragma unroll
            for (int mi = 0; mi < 4; mi++) {
                uint32_t ad = sb + AT_S_HI + kc*8192 + SWZ128((uint32_t)((mi*16 + rl)*128 + kg*16));
                LDSM4(Aa[mi][0], Aa[mi][1], Aa[mi][2], Aa[mi][3], ad);
            }
            #pragma unroll
            for (int np = 0; np < 4; np++) {
                uint32_t bd = stg + 0 + SWZ128((uint32_t)((wid*64 + np*16 + rl)*128 + kg*16));
                LDSM4(Bb[np][0], Bb[np][1], Bb[np][2], Bb[np][3], bd);
            }
            #pragma unroll
            for (int mi = 0; mi < 4; mi++)
                #pragma unroll
                for (int np = 0; np < 4; np++) {
                    MMABF(acc2[mi][2*np  ], Aa[mi], Bb[np][0], Bb[np][2]);
                    MMABF(acc2[mi][2*np+1], Aa[mi], Bb[np][1], Bb[np][3]);
                }
            #pragma unroll
            for (int mi = 0; mi < 4; mi++) {
                uint32_t ad = sb + AT_S_LO + kc*8192 + SWZ128((uint32_t)((mi*16 + rl)*128 + kg*16));
                LDSM4(Al2[mi][0], Al2[mi][1], Al2[mi][2], Al2[mi][3], ad);
            }
            #pragma unroll
            for (int mi = 0; mi < 4; mi++)
                #pragma unroll
                for (int np = 0; np < 4; np++) {
                    MMABF(acc2[mi][2*np  ], Al2[mi], Bb[np][0], Bb[np][2]);
                    MMABF(acc2[mi][2*np+1], Al2[mi], Bb[np][1], Bb[np][3]);
                }
            #pragma unroll
            for (int np = 0; np < 4; np++) {
                uint32_t bd = stg + 65536 + SWZ128((uint32_t)((wid*64 + np*16 + rl)*128 + kg*16));
                LDSM4(Bb[np][0], Bb[np][1], Bb[np][2], Bb[np][3], bd);
            }
            #pragma unroll
            for (int mi = 0; mi < 4; mi++)
                #pragma unroll
                for (int np = 0; np < 4; np++) {
                    MMABF(acc2[mi][2*np  ], Aa[mi], Bb[np][0], Bb[np][2]);
                    MMABF(acc2[mi][2*np+1], Aa[mi], Bb[np][1], Bb[np][3]);
                }
        }
        __syncthreads();
    }

    // epilogue: write depend fp32 + hi/lo, rows i < 200 only
    #pragma unroll
    for (int mi = 0; mi < 4; mi++)
        #pragma unroll
        for (int qh = 0; qh < 2; qh++) {
            int ig = t*64 + mi*16 + rbase + 8*qh;
            if (ig >= SL) continue;
            size_t rowo = (size_t)(b*SL + ig)*Hdim;
            #pragma unroll
            for (int nj = 0; nj < 8; nj++)
                #pragma unroll
                for (int q0 = 0; q0 < 2; q0++) {
                    int h = wid*64 + nj*8 + cbase + q0;
                    float v = acc2[mi][nj][qh*2 + q0];
                    g_depend[rowo + h] = v;
                    __nv_bfloat16 vh = __float2bfloat16(v);
                    g_dep_hi[rowo + h] = vh;
                    g_dep_lo[rowo + h] = __float2bfloat16(v - __bfloat162float(vh));
                }
        }
}

// ---------------- pool: map2 dot, masked softmax, a16 = pool*enc (fp16) --
__global__ __launch_bounds__(256) void pool_k(
    const float* __restrict__ wm2, const float* __restrict__ bm2)
{
    int b = blockIdx.x, tid = threadIdx.x, w = tid >> 5, l = tid & 31;
    __shared__ float m2[SL];
    __shared__ float red[8];
    int len = g_caslen[b];

    for (int i = w; i < SL; i += 8) {
        size_t r = (size_t)b*SL + i;
        float s = 0.f;
        #pragma unroll 4
        for (int h = l; h < Hdim; h += 32)
            s = fmaf(g_map1[r*Hdim + h] * g_ti[r*Hdim + h], wm2[h], s);
        for (int o = 16; o; o >>= 1) s += __shfl_xor_sync(0xffffffffu, s, o);
        if (l == 0) m2[i] = s + bm2[0];
    }
    __syncthreads();

    float mx = -1e30f;
    for (int i = tid; i < len; i += 256) mx = fmaxf(mx, m2[i]);
    for (int o = 16; o; o >>= 1) mx = fmaxf(mx, __shfl_xor_sync(0xffffffffu, mx, o));
    if (l == 0) red[w] = mx;
    __syncthreads();
    if (tid == 0) { float mm = red[0]; for (int q = 1; q < 8; q++) mm = fmaxf(mm, red[q]); red[0] = mm; }
    __syncthreads();
    mx = red[0];

    float sum = 0.f;
    for (int i = tid; i < len; i += 256) { float e = expf(m2[i] - mx); m2[i] = e; sum += e; }
    for (int o = 16; o; o >>= 1) sum += __shfl_xor_sync(0xffffffffu, sum, o);
    __syncthreads();
    if (l == 0) red[w] = sum;
    __syncthreads();
    if (tid == 0) { float t = 0.f; for (int q = 0; q < 8; q++) t += red[q]; red[0] = t; }
    __syncthreads();
    float inv = (len > 0) ? 1.f / red[0] : 0.f;

    for (int i = tid; i < SL; i += 256) m2[i] = (i < len) ? m2[i]*inv : 0.f;
    __syncthreads();

    size_t base = (size_t)b*SL*Hdim;
    for (int e = tid; e < SL*Hdim; e += 256) {
        int i = e >> 9;
        g_a16[base + e] = __float2half(m2[i] * g_enc[base + e]);
    }
}

// ---------------- final fp16 1-term GEMM ---------------------------------
#define FSTG 32768
#define SMEM_FG (2*FSTG)   // 65536

__device__ __forceinline__ void load_fin(uint32_t base, const __half* A, const __half* W, int tid){
    #pragma unroll
    for (int t = 0; t < 4; t++) {
        int G = tid + t*256; int r = G >> 3, g = G & 7;
        uint32_t d = SWZ128((uint32_t)(r*128 + g*16));
        cpa16(base + d,         A + (size_t)r*Hdim + g*8);
        cpa16(base + 16384 + d, W + (size_t)r*Hdim + g*8);
    }
    asm volatile("cp.async.commit_group;" ::: "memory");
}

__global__ __launch_bounds__(256, 2) void fgemm_k(
    const float* __restrict__ bias, float* __restrict__ C)
{
    extern __shared__ char smem[];
    const int tid = threadIdx.x, lane = tid & 31, wid = tid >> 5;
    const int bn = blockIdx.x, bm = blockIdx.y;
    const int wm = wid & 1, wn = wid >> 1;
    const int rl = lane & 15, gl = lane >> 4;
    uint32_t sb = smem_u32(smem);

    float acc[4][4][4];
    #pragma unroll
    for (int mi = 0; mi < 4; mi++)
        #pragma unroll
        for (int ni = 0; ni < 4; ni++)
            #pragma unroll
            for (int q = 0; q < 4; q++) acc[mi][ni][q] = 0.f;

    const __half* A0 = g_a16 + (size_t)(bm*128)*Hdim;
    const __half* W0 = g_w16 + (size_t)(bn*128)*Hdim;

    load_fin(sb,        A0,      W0,      tid);
    load_fin(sb + FSTG, A0 + 64, W0 + 64, tid);

    for (int kc = 0; kc < 8; kc++) {
        if (kc < 7) asm volatile("cp.async.wait_group 1;" ::: "memory");
        else        asm volatile("cp.async.wait_group 0;" ::: "memory");
        __syncthreads();
        const uint32_t base = sb + (kc & 1)*FSTG;
        #pragma unroll
        for (int ks = 0; ks < 4; ks++) {
            const int kg = 2*ks + gl;
            uint32_t Aa[4][4], Bb[2][4];
            #pragma unroll
            for (int mi = 0; mi < 4; mi++) {
                uint32_t ad = base + SWZ128((uint32_t)((wm*64 + mi*16 + rl)*128 + kg*16));
                LDSM4(Aa[mi][0], Aa[mi][1], Aa[mi][2], Aa[mi][3], ad);
            }
            #pragma unroll
            for (int np = 0; np < 2; np++) {
                uint32_t bd = base + 16384 + SWZ128((uint32_t)((wn*32 + np*16 + rl)*128 + kg*16));
                LDSM4(Bb[np][0], Bb[np][1], Bb[np][2], Bb[np][3], bd);
            }
            #pragma unroll
            for (int mi = 0; mi < 4; mi++)
                #pragma unroll
                for (int np = 0; np < 2; np++) {
                    MMAFP(acc[mi][2*np  ], Aa[mi], Bb[np][0], Bb[np][2]);
                    MMAFP(acc[mi][2*np+1], Aa[mi], Bb[np][1], Bb[np][3]);
                }
        }
        __syncthreads();
        if (kc + 2 < 8) load_fin(sb + (kc & 1)*FSTG, A0 + (kc+2)*64, W0 + (kc+2)*64, tid);
    }

    const int m0 = bm*128 + wm*64 + (lane >> 2);
    const int n0 = bn*128 + wn*32 + 2*(lane & 3);
    #pragma unroll
    for (int mi = 0; mi < 4; mi++) {
        int m = m0 + mi*16;
        #pragma unroll
        for (int ni = 0; ni < 4; ni++) {
            int n = n0 + ni*8;
            float b0 = bias[n], b1 = bias[n+1];
            float2 v0 = make_float2(acc[mi][ni][0] + b0, acc[mi][ni][1] + b1);
            float2 v1 = make_float2(acc[mi][ni][2] + b0, acc[mi][ni][3] + b1);
            *(float2*)(C + (size_t)m*Vdim + n)     = v0;
            *(float2*)(C + (size_t)(m+8)*Vdim + n) = v1;
        }
    }
}

// ---------------- launch ------------------------------------------------
extern "C" void kernel_launch(void* const* d_in, const int* in_sizes, int n_in,
                              void* d_out, int out_size)
{
    const int*   cas  = (const int*)  d_in[0];
    const int*   tii  = (const int*)  d_in[1];
    const float* emb  = (const float*)d_in[2];
    const float* tlam = (const float*)d_in[3];
    const float* w1   = (const float*)d_in[4];
    const float* b1   = (const float*)d_in[5];
    const float* wh   = (const float*)d_in[6];
    const float* bh   = (const float*)d_in[7];
    const float* wt   = (const float*)d_in[8];
    const float* bt   = (const float*)d_in[9];
    const float* wg   = (const float*)d_in[10];
    const float* bg   = (const float*)d_in[11];
    const float* wm1  = (const float*)d_in[12];
    const float* bm1  = (const float*)d_in[13];
    const float* wti  = (const float*)d_in[14];
    const float* bti  = (const float*)d_in[15];
    const float* wm2  = (const float*)d_in[16];
    const float* bm2  = (const float*)d_in[17];
    const float* wout = (const float*)d_in[18];
    const float* bout = (const float*)d_in[19];
    float* out = (float*)d_out;

    float *p_hidden, *p_map1, *p_ti, *p_enc;
    __nv_bfloat16 *p_emb_h, *p_emb_l, *p_tw_h, *p_tw_l, *p_hid_h, *p_hid_l;
    __nv_bfloat16 *p_hed_h, *p_hed_l, *p_tal_h, *p_tal_l;
    __nv_bfloat16 *p_dep_h, *p_dep_l, *p_enc_h, *p_enc_l;
    __nv_bfloat16 *p_w1h, *p_w1l, *p_whh, *p_whl, *p_wth, *p_wtl;
    __nv_bfloat16 *p_wm1h, *p_wm1l, *p_wtih, *p_wtil, *p_wgh, *p_wgl;
    __half *p_w16;
    cudaGetSymbolAddress((void**)&p_hidden, g_hidden);
    cudaGetSymbolAddress((void**)&p_map1,   g_map1);
    cudaGetSymbolAddress((void**)&p_ti,     g_ti);
    cudaGetSymbolAddress((void**)&p_enc,    g_enc);
    cudaGetSymbolAddress((void**)&p_emb_h,  g_emb_hi);
    cudaGetSymbolAddress((void**)&p_emb_l,  g_emb_lo);
    cudaGetSymbolAddress((void**)&p_tw_h,   g_tw_hi);
    cudaGetSymbolAddress((void**)&p_tw_l,   g_tw_lo);
    cudaGetSymbolAddress((void**)&p_hid_h,  g_hid_hi);
    cudaGetSymbolAddress((void**)&p_hid_l,  g_hid_lo);
    cudaGetSymbolAddress((void**)&p_hed_h,  g_hed_hi);
    cudaGetSymbolAddress((void**)&p_hed_l,  g_hed_lo);
    cudaGetSymbolAddress((void**)&p_tal_h,  g_tal_hi);
    cudaGetSymbolAddress((void**)&p_tal_l,  g_tal_lo);
    cudaGetSymbolAddress((void**)&p_dep_h,  g_dep_hi);
    cudaGetSymbolAddress((void**)&p_dep_l,  g_dep_lo);
    cudaGetSymbolAddress((void**)&p_enc_h,  g_enc_hi);
    cudaGetSymbolAddress((void**)&p_enc_l,  g_enc_lo);
    cudaGetSymbolAddress((void**)&p_w1h,    g_w1T_h);
    cudaGetSymbolAddress((void**)&p_w1l,    g_w1T_l);
    cudaGetSymbolAddress((void**)&p_whh,    g_whT_h);
    cudaGetSymbolAddress((void**)&p_whl,    g_whT_l);
    cudaGetSymbolAddress((void**)&p_wth,    g_wtT_h);
    cudaGetSymbolAddress((void**)&p_wtl,    g_wtT_l);
    cudaGetSymbolAddress((void**)&p_wm1h,   g_wm1T_h);
    cudaGetSymbolAddress((void**)&p_wm1l,   g_wm1T_l);
    cudaGetSymbolAddress((void**)&p_wtih,   g_wtiT_h);
    cudaGetSymbolAddress((void**)&p_wtil,   g_wtiT_l);
    cudaGetSymbolAddress((void**)&p_wgh,    g_wgT_h);
    cudaGetSymbolAddress((void**)&p_wgl,    g_wgT_l);
    cudaGetSymbolAddress((void**)&p_w16,    g_w16);

    cudaFuncSetAttribute(mgemm_k<0>, cudaFuncAttributeMaxDynamicSharedMemorySize, SMEM_MG);
    cudaFuncSetAttribute(mgemm_k<1>, cudaFuncAttributeMaxDynamicSharedMemorySize, SMEM_MG);
    cudaFuncSetAttribute(mgemm_k<2>, cudaFuncAttributeMaxDynamicSharedMemorySize, SMEM_MG);
    cudaFuncSetAttribute(mgemm_k<3>, cudaFuncAttributeMaxDynamicSharedMemorySize, SMEM_MG);
    cudaFuncSetAttribute(mgemm_k<4>, cudaFuncAttributeMaxDynamicSharedMemorySize, SMEM_MG);
    cudaFuncSetAttribute(attnmma_k,  cudaFuncAttributeMaxDynamicSharedMemorySize, SMEM_AT);
    cudaFuncSetAttribute(fgemm_k,    cudaFuncAttributeMaxDynamicSharedMemorySize, SMEM_FG);

    caslen_k<<<Bc, 256>>>(cas);

    // weight preprocessing
    transW_f16_k<<<dim3(Vdim/32, Hdim/32), dim3(32,8)>>>(wout, p_w16);
    transW_bf16_k<<<dim3(16,16), dim3(32,8)>>>(w1,  p_w1h,  p_w1l,  Hdim);
    transW_bf16_k<<<dim3(16,16), dim3(32,8)>>>(wh,  p_whh,  p_whl,  Hdim);
    transW_bf16_k<<<dim3(16,16), dim3(32,8)>>>(wt,  p_wth,  p_wtl,  Hdim);
    transW_bf16_k<<<dim3(16,16), dim3(32,8)>>>(wm1, p_wm1h, p_wm1l, Hdim);
    transW_bf16_k<<<dim3(16,16), dim3(32,8)>>>(wti, p_wtih, p_wtil, Hdim);
    transW_bf16_k<<<dim3(16,32), dim3(32,8)>>>(wg,  p_wgh,  p_wgl,  2*Hdim);

    // activation gathers + splits
    gatherSplit_k<<<(Mrows*Hdim)/256, 256>>>(emb,  cas, p_emb_h, p_emb_l);
    gatherSplit_k<<<(Mrows*Hdim)/256, 256>>>(tlam, tii, p_tw_h,  p_tw_l);

    dim3 gmid(Hdim/MGN, Mrows/MGM);    // (4, 50)
    // hidden = elu(emb@w1+b1)*mask (fp32 + splits)
    mgemm_k<1><<<gmid, 256, SMEM_MG>>>(p_emb_h, p_emb_l, p_emb_h, p_emb_l,
                                       p_w1h, p_w1l, Hdim, 8, b1,
                                       p_hidden, p_hid_h, p_hid_l);
    // hidden^T for attention GEMM2
    transHid_k<<<dim3(7, 16, Bc), dim3(32,8)>>>();
    // head / tail (splits only)
    mgemm_k<4><<<gmid, 256, SMEM_MG>>>(p_hid_h, p_hid_l, p_hid_h, p_hid_l,
                                       p_whh, p_whl, Hdim, 8, bh,
                                       nullptr, p_hed_h, p_hed_l);
    mgemm_k<4><<<gmid, 256, SMEM_MG>>>(p_hid_h, p_hid_l, p_hid_h, p_hid_l,
                                       p_wth, p_wtl, Hdim, 8, bt,
                                       nullptr, p_tal_h, p_tal_l);
    // attention via mma -> depend (fp32 + splits)
    attnmma_k<<<dim3(4, Bc), 256, SMEM_AT>>>();
    // gate -> enc (fp32 + splits)
    mgemm_k<3><<<gmid, 256, SMEM_MG>>>(p_hid_h, p_hid_l, p_dep_h, p_dep_l,
                                       p_wgh, p_wgl, 2*Hdim, 16, bg,
                                       p_enc, p_enc_h, p_enc_l);
    // map1, ti
    mgemm_k<2><<<gmid, 256, SMEM_MG>>>(p_enc_h, p_enc_l, p_enc_h, p_enc_l,
                                       p_wm1h, p_wm1l, Hdim, 8, bm1,
                                       p_map1, nullptr, nullptr);
    mgemm_k<2><<<gmid, 256, SMEM_MG>>>(p_tw_h, p_tw_l, p_tw_h, p_tw_l,
                                       p_wtih, p_wtil, Hdim, 8, bti,
                                       p_ti, nullptr, nullptr);
    // pool -> a16
    pool_k<<<Bc, 256>>>(wm2, bm2);
    // final GEMM
    fgemm_k<<<dim3(Vdim/128, Mrows/128), 256, SMEM_FG>>>(bout, out);
}